// round 5
// baseline (speedup 1.0000x reference)
#include <cuda_runtime.h>
#include <math.h>
#include <stdint.h>

// Model constants
#define BH      8
#define HDIM    64
#define DMODEL  512
#define SENC    2048
#define NB_ENC  2
#define SRTR    72
#define NB_RTR  64
#define NTOK_ENC 4096
#define NTOK_RTR 4608
#define FFH     1024

// Scratch layout (float offsets)
#define OFF_XN2   0ull                 // 4608*512*2
#define OFF_QKV   4718592ull           // 4608*1536
#define OFF_Q     11796480ull
#define OFF_K     14155776ull
#define OFF_V     16515072ull
#define OFF_ATT2  18874368ull          // 4608*512*2
#define OFF_H     23592960ull          // 4608*2048
#define OFF_ACT2  33030144ull          // 4608*1024*2
#define OFF_X     42467328ull
#define OFF_XR    44826624ull
#define OFF_ROWS2 47185920ull          // 512*512*2
#define OFF_OUT   47710208ull          // 512*256
#define OFF_KNR   47841280ull
#define OFF_KNG   47841792ull
#define OFF_RL    47842304ull
#define OFF_GL    47875072ull
#define OFF_WEQ2  47907840ull          // 4*512*1536*2
#define OFF_WEO2  54199296ull          // 4*512*512*2
#define OFF_WEU2  56296448ull          // 4*512*2048*2
#define OFF_WED2  64685056ull          // 4*1024*512*2
#define OFF_WRQ2  68879360ull          // 2*512*1536*2
#define OFF_WRO2  72025088ull
#define OFF_WRU2  73073664ull
#define OFF_WRD2  77267968ull
#define OFF_WOUT2 79365120ull          // 512*256*2
#define SCRATCH_FLOATS 79627264ull

__device__ float g_s[SCRATCH_FLOATS];

// ---------------- helpers ----------------
__device__ __forceinline__ float bsum128(float v, volatile float* red) {
    int tid = threadIdx.x;
    red[tid] = v;
    for (int off = 64; off >= 1; off >>= 1) {
        __syncthreads();
        if (tid < off) red[tid] += red[tid + off];
    }
    __syncthreads();
    float r = red[0];
    __syncthreads();
    return r;
}

__device__ __forceinline__ float bmax128(float v, volatile float* red) {
    int tid = threadIdx.x;
    red[tid] = v;
    for (int off = 64; off >= 1; off >>= 1) {
        __syncthreads();
        if (tid < off) red[tid] = fmaxf(red[tid], red[tid + off]);
    }
    __syncthreads();
    float r = red[0];
    __syncthreads();
    return r;
}

__device__ __forceinline__ uint32_t tf32_of(float x) {
    uint32_t u;
    asm("cvt.rna.tf32.f32 %0, %1;" : "=r"(u) : "f"(x));
    return u;
}

// split fp32 into tf32 hi + tf32 lo packed as float2
__device__ __forceinline__ float2 split2(float v) {
    uint32_t h = tf32_of(v);
    float hi = __uint_as_float(h);
    return make_float2(hi, __uint_as_float(tf32_of(v - hi)));
}

__device__ __forceinline__ void mma_tf32(float* c, const uint32_t* a, const uint32_t* b) {
    asm volatile(
        "mma.sync.aligned.m16n8k8.row.col.f32.tf32.tf32.f32 "
        "{%0,%1,%2,%3}, {%4,%5,%6,%7}, {%8,%9}, {%0,%1,%2,%3};"
        : "+f"(c[0]), "+f"(c[1]), "+f"(c[2]), "+f"(c[3])
        : "r"(a[0]), "r"(a[1]), "r"(a[2]), "r"(a[3]), "r"(b[0]), "r"(b[1]));
}

// ---------------- kernels ----------------
__global__ void copy_k(const float* __restrict__ src, float* __restrict__ dst, int n) {
    int i = blockIdx.x * blockDim.x + threadIdx.x;
    if (i < n) dst[i] = src[i];
}

// fp32 -> (tf32 hi, tf32 lo) pairs
__global__ void split_k(const float* __restrict__ w, float2* __restrict__ w2, int n) {
    int i = blockIdx.x * blockDim.x + threadIdx.x;
    if (i < n) w2[i] = split2(w[i]);
}

// rmsnorm, writes pre-split float2. One block (128 thr) per token.
__global__ void rmsnorm_k(const float* __restrict__ x, const float* __restrict__ w,
                          float2* __restrict__ y2) {
    __shared__ float red[128];
    size_t row = (size_t)blockIdx.x * DMODEL;
    int tid = threadIdx.x;
    float ss = 0.f;
    for (int i = tid; i < DMODEL; i += 128) {
        float v = x[row + i];
        ss += v * v;
    }
    float tot = bsum128(ss, red);
    float scale = rsqrtf(tot / (float)DMODEL + 1e-6f);
    for (int i = tid; i < DMODEL; i += 128)
        y2[row + i] = split2(x[row + i] * scale * w[i]);
}

// ---- Tensor-core 3xTF32 GEMM on pre-split operands ----
// C[M,N] = (accum? C : 0) + A[M,K] @ B[K,N], where A2/B2 hold (hi,lo) float2.
// M,N multiples of 128; K multiple of 16.
// Block 256 thr (8 warps, 2x4), tile 128x128, BK=16, double-buffered smem.
#define AST 20    // A smem row stride in float2 (==4 mod 16 -> conflict-free LDS.64)
#define BST 132   // B smem row stride in float2 (==4 mod 16)
__global__ __launch_bounds__(256) void sgemm_tc(const float2* __restrict__ A2,
                                                const float2* __restrict__ B2,
                                                float* __restrict__ C,
                                                int M, int N, int K, int accum) {
    __shared__ __align__(16) float2 As[2][128][AST];
    __shared__ __align__(16) float2 Bs[2][16][BST];
    int tid = threadIdx.x;
    int lane = tid & 31, warp = tid >> 5;
    int wm = warp >> 2, wn = warp & 3;
    int grp = lane >> 2, qid = lane & 3;
    int bm = blockIdx.y * 128, bn = blockIdx.x * 128;

    float acc[4][4][4];
#pragma unroll
    for (int i = 0; i < 4; i++)
#pragma unroll
        for (int j = 0; j < 4; j++)
#pragma unroll
            for (int t = 0; t < 4; t++) acc[i][j][t] = 0.f;

    int arow = tid >> 1, akh = (tid & 1) * 8;   // A: 2 thr/row, 8 float2 each
    int bk = tid >> 4, bcol = (tid & 15) * 8;   // B: 16 thr/row, 8 float2 each
    float4 pa[4], pb[4];

#define LOAD(k0)                                                                  \
    {                                                                             \
        const float4* ap = (const float4*)(A2 + (size_t)(bm + arow) * K + (k0) + akh); \
        pa[0] = ap[0]; pa[1] = ap[1]; pa[2] = ap[2]; pa[3] = ap[3];               \
        const float4* bp = (const float4*)(B2 + (size_t)((k0) + bk) * N + bn + bcol); \
        pb[0] = bp[0]; pb[1] = bp[1]; pb[2] = bp[2]; pb[3] = bp[3];               \
    }
#define STORE(buf)                                                                \
    {                                                                             \
        float4* as = (float4*)&As[buf][arow][akh];                                \
        as[0] = pa[0]; as[1] = pa[1]; as[2] = pa[2]; as[3] = pa[3];               \
        float4* bs = (float4*)&Bs[buf][bk][bcol];                                 \
        bs[0] = pb[0]; bs[1] = pb[1]; bs[2] = pb[2]; bs[3] = pb[3];               \
    }

    LOAD(0);
    STORE(0);
    __syncthreads();

    int nk = K >> 4;
    for (int kt = 0; kt < nk; kt++) {
        int buf = kt & 1;
        if (kt + 1 < nk) LOAD((kt + 1) << 4);
#pragma unroll
        for (int kk = 0; kk < 16; kk += 8) {
            float2 a[4][4], b[4][2];
#pragma unroll
            for (int mt = 0; mt < 4; mt++) {
                int r0 = wm * 64 + mt * 16 + grp;
                a[mt][0] = As[buf][r0][kk + qid];
                a[mt][1] = As[buf][r0 + 8][kk + qid];
                a[mt][2] = As[buf][r0][kk + qid + 4];
                a[mt][3] = As[buf][r0 + 8][kk + qid + 4];
            }
#pragma unroll
            for (int nt = 0; nt < 4; nt++) {
                int c0 = wn * 32 + nt * 8 + grp;
                b[nt][0] = Bs[buf][kk + qid][c0];
                b[nt][1] = Bs[buf][kk + qid + 4][c0];
            }
#pragma unroll
            for (int mt = 0; mt < 4; mt++) {
                uint32_t ah[4], al[4];
#pragma unroll
                for (int t = 0; t < 4; t++) {
                    ah[t] = __float_as_uint(a[mt][t].x);
                    al[t] = __float_as_uint(a[mt][t].y);
                }
#pragma unroll
                for (int nt = 0; nt < 4; nt++) {
                    uint32_t bh[2], bl[2];
                    bh[0] = __float_as_uint(b[nt][0].x);
                    bh[1] = __float_as_uint(b[nt][1].x);
                    bl[0] = __float_as_uint(b[nt][0].y);
                    bl[1] = __float_as_uint(b[nt][1].y);
                    mma_tf32(acc[mt][nt], al, bh);
                    mma_tf32(acc[mt][nt], ah, bl);
                    mma_tf32(acc[mt][nt], ah, bh);
                }
            }
        }
        if (kt + 1 < nk) STORE(buf ^ 1);
        __syncthreads();
    }

#pragma unroll
    for (int mt = 0; mt < 4; mt++) {
#pragma unroll
        for (int nt = 0; nt < 4; nt++) {
            int r0 = bm + wm * 64 + mt * 16 + grp;
            int c0 = bn + wn * 32 + nt * 8 + 2 * qid;
            size_t i00 = (size_t)r0 * N + c0;
            size_t i10 = (size_t)(r0 + 8) * N + c0;
            if (accum) {
                C[i00]     += acc[mt][nt][0];
                C[i00 + 1] += acc[mt][nt][1];
                C[i10]     += acc[mt][nt][2];
                C[i10 + 1] += acc[mt][nt][3];
            } else {
                C[i00]     = acc[mt][nt][0];
                C[i00 + 1] = acc[mt][nt][1];
                C[i10]     = acc[mt][nt][2];
                C[i10 + 1] = acc[mt][nt][3];
            }
        }
    }
#undef LOAD
#undef STORE
}

// qkv row -> q/k (RoPE) and v, layout [bh][SEQ][64]. grid=ntok, block=256
__global__ void split_rope_k(const float* __restrict__ qkv,
                             float* __restrict__ Q, float* __restrict__ K,
                             float* __restrict__ V, int SEQ) {
    int tok = blockIdx.x;
    int b = tok / SEQ, s = tok % SEQ;
    const float* row = qkv + (size_t)tok * 1536;
    int tid = threadIdx.x;
    int h = tid >> 5, i = tid & 31;
    float q1 = row[h * 64 + i], q2 = row[h * 64 + i + 32];
    float k1 = row[512 + h * 64 + i], k2 = row[512 + h * 64 + i + 32];
    float inv = powf(1e-4f, (float)i * (1.0f / 32.0f));
    float ang = (float)s * inv;
    float c = cosf(ang), sn = sinf(ang);
    size_t base = ((size_t)(b * BH + h) * SEQ + s) * 64;
    Q[base + i]      =  q1 * c + q2 * sn;
    Q[base + i + 32] = -q1 * sn + q2 * c;
    K[base + i]      =  k1 * c + k2 * sn;
    K[base + i + 32] = -k1 * sn + k2 * c;
    for (int j = tid; j < 512; j += 256) {
        int hh = j >> 6, dd = j & 63;
        V[((size_t)(b * BH + hh) * SEQ + s) * 64 + dd] = row[1024 + j];
    }
}

// attention; output written pre-split (float2) for the O-projection GEMM.
__global__ __launch_bounds__(128) void attn_k(const float* __restrict__ Q,
                                              const float* __restrict__ K,
                                              const float* __restrict__ V,
                                              float2* __restrict__ O2,
                                              const int* __restrict__ doc,
                                              int SEQ, int maskmode) {
    __shared__ float sq[64];
    __shared__ float sp[2048];
    __shared__ float red[128];
    int q = blockIdx.x;
    int bh = blockIdx.y;
    int b = bh / BH, h = bh % BH;
    int tid = threadIdx.x;
    const float* Qr = Q + ((size_t)bh * SEQ + q) * 64;
    if (tid < 64) sq[tid] = Qr[tid];
    __syncthreads();

    int kend = SEQ;
    int mydoc = 0;
    if (maskmode == 1) {
        kend = ((q >> 6) + 1) << 6;
        mydoc = doc[b * SEQ + q];
    }
    float m = -1e30f;
    for (int k = tid; k < kend; k += 128) {
        float s = -1e30f;
        bool ok = (maskmode == 0) || (doc[b * SEQ + k] == mydoc);
        if (ok) {
            const float4* kr = (const float4*)(K + ((size_t)bh * SEQ + k) * 64);
            const float4* qr = (const float4*)sq;
            float a = 0.f;
#pragma unroll
            for (int i = 0; i < 16; i++) {
                float4 kv = kr[i], qv = qr[i];
                a += kv.x * qv.x + kv.y * qv.y + kv.z * qv.z + kv.w * qv.w;
            }
            s = a * 0.125f;
        }
        sp[k] = s;
        m = fmaxf(m, s);
    }
    m = bmax128(m, red);

    float l = 0.f;
    for (int k = tid; k < kend; k += 128) {
        float e = expf(sp[k] - m);
        sp[k] = e;
        l += e;
    }
    l = bsum128(l, red);

    int d = tid & 63, half = tid >> 6;
    float acc = 0.f;
    for (int k = half; k < kend; k += 2)
        acc += sp[k] * V[((size_t)bh * SEQ + k) * 64 + d];
    red[tid] = acc;
    __syncthreads();
    if (tid < 64) {
        float o = (red[tid] + red[tid + 64]) / l;
        O2[(size_t)(b * SEQ + q) * DMODEL + h * 64 + tid] = split2(o);
    }
}

__global__ void silu_k(const float* __restrict__ hbuf, float2* __restrict__ act2, int n) {
    int i = blockIdx.x * blockDim.x + threadIdx.x;
    if (i >= n) return;
    int t = i >> 10, j = i & 1023;
    float a = hbuf[(size_t)t * 2048 + j];
    float b = hbuf[(size_t)t * 2048 + 1024 + j];
    act2[i] = split2((a / (1.0f + expf(-a))) * b);
}

__global__ void build_xr_k(const float* __restrict__ x, const float* __restrict__ rt,
                           float* __restrict__ xr) {
    int i = blockIdx.x * blockDim.x + threadIdx.x;
    if (i >= NTOK_RTR * DMODEL) return;
    int blk = i / (SRTR * DMODEL);
    int rem = i % (SRTR * DMODEL);
    int t = rem / DMODEL, dd = rem % DMODEL;
    xr[i] = (t < 64) ? x[(size_t)(blk * 64 + t) * DMODEL + dd]
                     : rt[(size_t)(t - 64) * DMODEL + dd];
}

__global__ void gather_rows_k(const float* __restrict__ xr, float2* __restrict__ rows2) {
    int i = blockIdx.x * blockDim.x + threadIdx.x;
    if (i >= 512 * DMODEL) return;
    int row = i / DMODEL, dd = i % DMODEL;
    int blk = row >> 3, r = row & 7;
    rows2[i] = split2(xr[((size_t)blk * SRTR + 64 + r) * DMODEL + dd]);
}

__global__ void knorm_k(const float* __restrict__ kr, const float* __restrict__ kg,
                        float* __restrict__ knr, float* __restrict__ kng) {
    int tid = threadIdx.x;
    int which = tid >> 9;
    int idx = tid & 511;
    int g = idx >> 4, e = idx & 15;
    const float* src = which ? kg : kr;
    const float* col = src + (size_t)g * 128 * 16 + e;
    float s = 0.f;
    for (int d = 0; d < 128; d++) { float v = col[d * 16]; s += v * v; }
    float n = fmaxf(sqrtf(s), 1e-12f);
    if (which) kng[idx] = n; else knr[idx] = n;
}

__global__ void logits_k(const float* __restrict__ outp,
                         const float* __restrict__ keys_r, const float* __restrict__ keys_g,
                         const float* __restrict__ knr, const float* __restrict__ kng,
                         float* __restrict__ rl, float* __restrict__ gl) {
    __shared__ float vr[128], vg[128], red[128];
    int g = blockIdx.x >> 6, bb = blockIdx.x & 63;
    int b = bb >> 5, l = bb & 31;
    int srcl = (l + 31) & 31;
    int r = g >> 2;
    const float* row = outp + (size_t)((b * 32 + srcl) * 8 + r) * 256;
    int tid = threadIdx.x;
    vr[tid] = row[tid];
    vg[tid] = row[128 + tid];
    float nr2 = bsum128(vr[tid] * vr[tid], red);
    float ng2 = bsum128(vg[tid] * vg[tid], red);
    float inr = 1.0f / fmaxf(sqrtf(nr2), 1e-12f);
    float ing = 1.0f / fmaxf(sqrtf(ng2), 1e-12f);
    if (tid < 16) {
        int e = tid;
        const float* kr = keys_r + (size_t)g * 128 * 16 + e;
        const float* kg = keys_g + (size_t)g * 128 * 16 + e;
        float dr = 0.f, dg = 0.f;
        for (int dd = 0; dd < 128; dd++) {
            dr += vr[dd] * kr[dd * 16];
            dg += vg[dd] * kg[dd * 16];
        }
        rl[(size_t)(g * 64 + bb) * 16 + e] = dr * inr / knr[g * 16 + e];
        gl[(size_t)(g * 64 + bb) * 16 + e] = dg * ing / kng[g * 16 + e];
    }
}

__global__ void topk_k(const float* __restrict__ rl, const float* __restrict__ gl,
                       float* __restrict__ out) {
    int t = blockIdx.x * blockDim.x + threadIdx.x;
    if (t >= 2048) return;
    const float* r = rl + (size_t)t * 16;
    const float* g = gl + (size_t)t * 16;
    int i1 = 0; float v1 = r[0];
    for (int e = 1; e < 16; e++) if (r[e] > v1) { v1 = r[e]; i1 = e; }
    int i2 = -1; float v2 = -1e30f;
    for (int e = 0; e < 16; e++) {
        if (e == i1) continue;
        if (r[e] > v2) { v2 = r[e]; i2 = e; }
    }
    out[(size_t)t * 2 + 0] = v1;
    out[(size_t)t * 2 + 1] = v2;
    out[4096 + (size_t)t * 2 + 0] = g[i1];
    out[4096 + (size_t)t * 2 + 1] = g[i2];
}

// ---------------- host orchestration ----------------
static void run_layer(float* cur, const float2* qkvw2, const float2* ow2,
                      const float2* upw2, const float2* dw2,
                      const float* n1, const float* n2,
                      int ntok, int NB, int SEQ, int maskmode, const int* doc,
                      float* sb) {
    float2* xn2  = (float2*)(sb + OFF_XN2);
    float*  qkv  = sb + OFF_QKV;
    float*  qb   = sb + OFF_Q;
    float*  kb   = sb + OFF_K;
    float*  vb   = sb + OFF_V;
    float2* att2 = (float2*)(sb + OFF_ATT2);
    float*  hb   = sb + OFF_H;
    float2* act2 = (float2*)(sb + OFF_ACT2);

    rmsnorm_k<<<ntok, 128>>>(cur, n1, xn2);
    sgemm_tc<<<dim3(1536 / 128, ntok / 128), 256>>>(xn2, qkvw2, qkv, ntok, 1536, 512, 0);
    split_rope_k<<<ntok, 256>>>(qkv, qb, kb, vb, SEQ);
    attn_k<<<dim3(SEQ, NB * BH), 128>>>(qb, kb, vb, att2, doc, SEQ, maskmode);
    sgemm_tc<<<dim3(512 / 128, ntok / 128), 256>>>(att2, ow2, cur, ntok, 512, 512, 1);
    rmsnorm_k<<<ntok, 128>>>(cur, n2, xn2);
    sgemm_tc<<<dim3(2048 / 128, ntok / 128), 256>>>(xn2, upw2, hb, ntok, 2048, 512, 0);
    silu_k<<<(ntok * 1024 + 255) / 256, 256>>>(hb, act2, ntok * 1024);
    sgemm_tc<<<dim3(512 / 128, ntok / 128), 256>>>(act2, dw2, cur, ntok, 512, 1024, 1);
}

extern "C" void kernel_launch(void* const* d_in, const int* in_sizes, int n_in,
                              void* d_out, int out_size) {
    const float* x_in   = (const float*)d_in[0];
    const int*   doc    = (const int*)d_in[1];
    const float* rt     = (const float*)d_in[2];
    const float* out_w  = (const float*)d_in[3];
    const float* keys_r = (const float*)d_in[4];
    const float* keys_g = (const float*)d_in[5];
    const float* e_qkv  = (const float*)d_in[6];
    const float* e_o    = (const float*)d_in[7];
    const float* e_up   = (const float*)d_in[8];
    const float* e_dn   = (const float*)d_in[9];
    const float* e_n1   = (const float*)d_in[10];
    const float* e_n2   = (const float*)d_in[11];
    const float* r_qkv  = (const float*)d_in[12];
    const float* r_o    = (const float*)d_in[13];
    const float* r_up   = (const float*)d_in[14];
    const float* r_dn   = (const float*)d_in[15];
    const float* r_n1   = (const float*)d_in[16];
    const float* r_n2   = (const float*)d_in[17];
    float* out = (float*)d_out;

    float* sb;
    cudaGetSymbolAddress((void**)&sb, g_s);
    float*  xbuf  = sb + OFF_X;
    float*  xr    = sb + OFF_XR;
    float2* rows2 = (float2*)(sb + OFF_ROWS2);
    float*  outp  = sb + OFF_OUT;
    float*  knr   = sb + OFF_KNR;
    float*  kng   = sb + OFF_KNG;
    float*  rl    = sb + OFF_RL;
    float*  gl    = sb + OFF_GL;

    float2* weq2 = (float2*)(sb + OFF_WEQ2);
    float2* weo2 = (float2*)(sb + OFF_WEO2);
    float2* weu2 = (float2*)(sb + OFF_WEU2);
    float2* wed2 = (float2*)(sb + OFF_WED2);
    float2* wrq2 = (float2*)(sb + OFF_WRQ2);
    float2* wro2 = (float2*)(sb + OFF_WRO2);
    float2* wru2 = (float2*)(sb + OFF_WRU2);
    float2* wrd2 = (float2*)(sb + OFF_WRD2);
    float2* wout2 = (float2*)(sb + OFF_WOUT2);

    // pre-split all weights (one pass, memory-bound)
    split_k<<<(4 * 512 * 1536 + 255) / 256, 256>>>(e_qkv, weq2, 4 * 512 * 1536);
    split_k<<<(4 * 512 * 512 + 255) / 256, 256>>>(e_o, weo2, 4 * 512 * 512);
    split_k<<<(4 * 512 * 2048 + 255) / 256, 256>>>(e_up, weu2, 4 * 512 * 2048);
    split_k<<<(4 * 1024 * 512 + 255) / 256, 256>>>(e_dn, wed2, 4 * 1024 * 512);
    split_k<<<(2 * 512 * 1536 + 255) / 256, 256>>>(r_qkv, wrq2, 2 * 512 * 1536);
    split_k<<<(2 * 512 * 512 + 255) / 256, 256>>>(r_o, wro2, 2 * 512 * 512);
    split_k<<<(2 * 512 * 2048 + 255) / 256, 256>>>(r_up, wru2, 2 * 512 * 2048);
    split_k<<<(2 * 1024 * 512 + 255) / 256, 256>>>(r_dn, wrd2, 2 * 1024 * 512);
    split_k<<<(512 * 256 + 255) / 256, 256>>>(out_w, wout2, 512 * 256);

    copy_k<<<(NTOK_ENC * DMODEL + 255) / 256, 256>>>(x_in, xbuf, NTOK_ENC * DMODEL);

    for (int i = 0; i < 4; i++) {
        run_layer(xbuf,
                  weq2 + (size_t)i * 512 * 1536,
                  weo2 + (size_t)i * 512 * 512,
                  weu2 + (size_t)i * 512 * 2048,
                  wed2 + (size_t)i * 1024 * 512,
                  e_n1 + (size_t)i * 512,
                  e_n2 + (size_t)i * 512,
                  NTOK_ENC, NB_ENC, SENC, 1, doc, sb);
    }

    build_xr_k<<<(NTOK_RTR * DMODEL + 255) / 256, 256>>>(xbuf, rt, xr);

    for (int i = 0; i < 2; i++) {
        run_layer(xr,
                  wrq2 + (size_t)i * 512 * 1536,
                  wro2 + (size_t)i * 512 * 512,
                  wru2 + (size_t)i * 512 * 2048,
                  wrd2 + (size_t)i * 1024 * 512,
                  r_n1 + (size_t)i * 512,
                  r_n2 + (size_t)i * 512,
                  NTOK_RTR, NB_RTR, SRTR, 0, nullptr, sb);
    }

    gather_rows_k<<<(512 * DMODEL + 255) / 256, 256>>>(xr, rows2);
    sgemm_tc<<<dim3(256 / 128, 512 / 128), 256>>>(rows2, wout2, outp, 512, 256, 512, 0);

    knorm_k<<<1, 1024>>>(keys_r, keys_g, knr, kng);
    logits_k<<<32 * 64, 128>>>(outp, keys_r, keys_g, knr, kng, rl, gl);
    topk_k<<<16, 128>>>(rl, gl, out);
}

// round 6
// speedup vs baseline: 1.2217x; 1.2217x over previous
#include <cuda_runtime.h>
#include <cuda_fp16.h>
#include <math.h>
#include <stdint.h>

// Model constants
#define BH      8
#define HDIM    64
#define DMODEL  512
#define SENC    2048
#define SRTR    72
#define NTOK_ENC 4096
#define NTOK_RTR 4608
#define FFH     1024

// ---- fp32 scratch (float offsets) ----
#define OFF_QKV   0ull                 // 4608*1536
#define OFF_Q     7077888ull
#define OFF_K     9437184ull
#define OFF_V     11796480ull
#define OFF_H     14155776ull          // 4608*2048
#define OFF_X     23592960ull
#define OFF_XR    25952256ull
#define OFF_OUT   28311552ull          // 512*256
#define OFF_KNR   28442624ull
#define OFF_KNG   28443136ull
#define OFF_RL    28443648ull
#define OFF_GL    28476416ull
#define SCRATCH_FLOATS 28509184ull
__device__ float g_s[SCRATCH_FLOATS];

// ---- fp16 scratch (half offsets) ----
#define HO_XNH   0ull                  // 4608*512
#define HO_XNL   2359296ull
#define HO_ATTH  4718592ull
#define HO_ATTL  7077888ull
#define HO_ACTH  9437184ull            // 4608*1024
#define HO_ACTL  14155776ull
#define HO_ROWSH 18874368ull           // 512*512
#define HO_ROWSL 19136512ull
#define HO_WH    19398656ull           // all weights (transposed), 15859712 halves
#define HO_WL    35258368ull
#define SCRATCH_HALVES 51118080ull
__device__ __half g_h[SCRATCH_HALVES];

// weight-plane sub-offsets (halves)
#define WO_EQ   0ull         // 4 x [1536][512]
#define WO_EO   3145728ull   // 4 x [512][512]
#define WO_EU   4194304ull   // 4 x [2048][512]
#define WO_ED   8388608ull   // 4 x [512][1024]
#define WO_RQ   10485760ull
#define WO_RO   12058624ull
#define WO_RU   12582912ull
#define WO_RD   14680064ull
#define WO_OUT  15728640ull  // [256][512]

// ---------------- helpers ----------------
__device__ __forceinline__ float bsum128(float v, volatile float* red) {
    int tid = threadIdx.x;
    red[tid] = v;
    for (int off = 64; off >= 1; off >>= 1) {
        __syncthreads();
        if (tid < off) red[tid] += red[tid + off];
    }
    __syncthreads();
    float r = red[0];
    __syncthreads();
    return r;
}

__device__ __forceinline__ float bmax128(float v, volatile float* red) {
    int tid = threadIdx.x;
    red[tid] = v;
    for (int off = 64; off >= 1; off >>= 1) {
        __syncthreads();
        if (tid < off) red[tid] = fmaxf(red[tid], red[tid + off]);
    }
    __syncthreads();
    float r = red[0];
    __syncthreads();
    return r;
}

// fp32 -> fp16 hi + fp16 lo
__device__ __forceinline__ void split_h(float v, __half& hi, __half& lo) {
    hi = __float2half_rn(v);
    lo = __float2half_rn(v - __half2float(hi));
}

__device__ __forceinline__ void mma16816(float* c, const uint32_t* a, const uint32_t* b) {
    asm volatile(
        "mma.sync.aligned.m16n8k16.row.col.f32.f16.f16.f32 "
        "{%0,%1,%2,%3}, {%4,%5,%6,%7}, {%8,%9}, {%0,%1,%2,%3};"
        : "+f"(c[0]), "+f"(c[1]), "+f"(c[2]), "+f"(c[3])
        : "r"(a[0]), "r"(a[1]), "r"(a[2]), "r"(a[3]), "r"(b[0]), "r"(b[1]));
}

// ---------------- kernels ----------------
__global__ void copy_k(const float* __restrict__ src, float* __restrict__ dst, int n) {
    int i = blockIdx.x * blockDim.x + threadIdx.x;
    if (i < n) dst[i] = src[i];
}

// transpose + split: w[K][N] fp32 -> hT[N][K], lT[N][K] halves. grid(N/32,K/32) block(32,8)
__global__ void wsplitT_k(const float* __restrict__ w, __half* __restrict__ hT,
                          __half* __restrict__ lT, int K, int N) {
    __shared__ float t[32][33];
    int n0 = blockIdx.x * 32, k0 = blockIdx.y * 32;
    int tx = threadIdx.x, ty = threadIdx.y;
    for (int i = ty; i < 32; i += 8)
        t[i][tx] = w[(size_t)(k0 + i) * N + n0 + tx];
    __syncthreads();
    for (int i = ty; i < 32; i += 8) {
        float v = t[tx][i];                       // = w[k0+tx][n0+i]
        __half h, l;
        split_h(v, h, l);
        hT[(size_t)(n0 + i) * K + k0 + tx] = h;
        lT[(size_t)(n0 + i) * K + k0 + tx] = l;
    }
}

// rmsnorm -> hi/lo half planes. One block (128 thr) per token.
__global__ void rmsnorm_k(const float* __restrict__ x, const float* __restrict__ w,
                          __half* __restrict__ yh, __half* __restrict__ yl) {
    __shared__ float red[128];
    size_t row = (size_t)blockIdx.x * DMODEL;
    int tid = threadIdx.x;
    float ss = 0.f;
    for (int i = tid; i < DMODEL; i += 128) {
        float v = x[row + i];
        ss += v * v;
    }
    float tot = bsum128(ss, red);
    float scale = rsqrtf(tot / (float)DMODEL + 1e-6f);
    for (int i = tid; i < DMODEL; i += 128) {
        __half h, l;
        split_h(x[row + i] * scale * w[i], h, l);
        yh[row + i] = h;
        yl[row + i] = l;
    }
}

// ---- 3xFP16 split GEMM on tensor cores ----
// C[M,N] = (accum? C : 0) + A[M,K] @ B[K,N]
// A given as hi/lo half planes [M][K]; B as transposed hi/lo planes [N][K].
// M,N multiples of 128; K multiple of 16. Block 256 thr (8 warps, 2x4),
// tile 128x128, BK=16, double-buffered. Stride 24 halves: conflict-free LDS.32.
__global__ __launch_bounds__(256) void sgemm_h3(const __half* __restrict__ Ah,
                                                const __half* __restrict__ Al,
                                                const __half* __restrict__ BTh,
                                                const __half* __restrict__ BTl,
                                                float* __restrict__ C,
                                                int M, int N, int K, int accum) {
    __shared__ __align__(16) __half As[2][2][128][24];   // [buf][plane][row][k]
    __shared__ __align__(16) __half Bs[2][2][128][24];   // [buf][plane][n][k]
    int tid = threadIdx.x;
    int lane = tid & 31, warp = tid >> 5;
    int wm = warp >> 2, wn = warp & 3;
    int grp = lane >> 2, qid = lane & 3;
    int bm = blockIdx.y * 128, bn = blockIdx.x * 128;

    float acc[4][4][4];
#pragma unroll
    for (int i = 0; i < 4; i++)
#pragma unroll
        for (int j = 0; j < 4; j++)
#pragma unroll
            for (int t = 0; t < 4; t++) acc[i][j][t] = 0.f;

    int lrow = tid >> 1, lseg = (tid & 1) * 8;
    uint4 pah, pal, pbh, pbl;

#define LOAD(k0)                                                                   \
    {                                                                              \
        pah = *(const uint4*)(Ah + (size_t)(bm + lrow) * K + (k0) + lseg);         \
        pal = *(const uint4*)(Al + (size_t)(bm + lrow) * K + (k0) + lseg);         \
        pbh = *(const uint4*)(BTh + (size_t)(bn + lrow) * K + (k0) + lseg);        \
        pbl = *(const uint4*)(BTl + (size_t)(bn + lrow) * K + (k0) + lseg);        \
    }
#define STORE(buf)                                                                 \
    {                                                                              \
        *(uint4*)&As[buf][0][lrow][lseg] = pah;                                    \
        *(uint4*)&As[buf][1][lrow][lseg] = pal;                                    \
        *(uint4*)&Bs[buf][0][lrow][lseg] = pbh;                                    \
        *(uint4*)&Bs[buf][1][lrow][lseg] = pbl;                                    \
    }

    LOAD(0);
    STORE(0);
    __syncthreads();

    int nk = K >> 4;
    for (int kt = 0; kt < nk; kt++) {
        int buf = kt & 1;
        if (kt + 1 < nk) LOAD((kt + 1) << 4);

        uint32_t ah[4][4], al[4][4], bh[4][2], bl[4][2];
#pragma unroll
        for (int mt = 0; mt < 4; mt++) {
            int r0 = wm * 64 + mt * 16 + grp;
            ah[mt][0] = *(const uint32_t*)&As[buf][0][r0][2 * qid];
            ah[mt][1] = *(const uint32_t*)&As[buf][0][r0 + 8][2 * qid];
            ah[mt][2] = *(const uint32_t*)&As[buf][0][r0][2 * qid + 8];
            ah[mt][3] = *(const uint32_t*)&As[buf][0][r0 + 8][2 * qid + 8];
            al[mt][0] = *(const uint32_t*)&As[buf][1][r0][2 * qid];
            al[mt][1] = *(const uint32_t*)&As[buf][1][r0 + 8][2 * qid];
            al[mt][2] = *(const uint32_t*)&As[buf][1][r0][2 * qid + 8];
            al[mt][3] = *(const uint32_t*)&As[buf][1][r0 + 8][2 * qid + 8];
        }
#pragma unroll
        for (int nt = 0; nt < 4; nt++) {
            int c0 = wn * 32 + nt * 8 + grp;
            bh[nt][0] = *(const uint32_t*)&Bs[buf][0][c0][2 * qid];
            bh[nt][1] = *(const uint32_t*)&Bs[buf][0][c0][2 * qid + 8];
            bl[nt][0] = *(const uint32_t*)&Bs[buf][1][c0][2 * qid];
            bl[nt][1] = *(const uint32_t*)&Bs[buf][1][c0][2 * qid + 8];
        }
#pragma unroll
        for (int mt = 0; mt < 4; mt++)
#pragma unroll
            for (int nt = 0; nt < 4; nt++) {
                mma16816(acc[mt][nt], al[mt], bh[nt]);
                mma16816(acc[mt][nt], ah[mt], bl[nt]);
                mma16816(acc[mt][nt], ah[mt], bh[nt]);
            }
        if (kt + 1 < nk) STORE(buf ^ 1);
        __syncthreads();
    }

#pragma unroll
    for (int mt = 0; mt < 4; mt++) {
#pragma unroll
        for (int nt = 0; nt < 4; nt++) {
            int r0 = bm + wm * 64 + mt * 16 + grp;
            int c0 = bn + wn * 32 + nt * 8 + 2 * qid;
            size_t i00 = (size_t)r0 * N + c0;
            size_t i10 = (size_t)(r0 + 8) * N + c0;
            if (accum) {
                C[i00]     += acc[mt][nt][0];
                C[i00 + 1] += acc[mt][nt][1];
                C[i10]     += acc[mt][nt][2];
                C[i10 + 1] += acc[mt][nt][3];
            } else {
                C[i00]     = acc[mt][nt][0];
                C[i00 + 1] = acc[mt][nt][1];
                C[i10]     = acc[mt][nt][2];
                C[i10 + 1] = acc[mt][nt][3];
            }
        }
    }
#undef LOAD
#undef STORE
}

// qkv row -> q/k (RoPE) and v, layout [bh][SEQ][64]. grid=ntok, block=256
__global__ void split_rope_k(const float* __restrict__ qkv,
                             float* __restrict__ Q, float* __restrict__ K,
                             float* __restrict__ V, int SEQ) {
    int tok = blockIdx.x;
    int b = tok / SEQ, s = tok % SEQ;
    const float* row = qkv + (size_t)tok * 1536;
    int tid = threadIdx.x;
    int h = tid >> 5, i = tid & 31;
    float q1 = row[h * 64 + i], q2 = row[h * 64 + i + 32];
    float k1 = row[512 + h * 64 + i], k2 = row[512 + h * 64 + i + 32];
    float inv = powf(1e-4f, (float)i * (1.0f / 32.0f));
    float ang = (float)s * inv;
    float c = cosf(ang), sn = sinf(ang);
    size_t base = ((size_t)(b * BH + h) * SEQ + s) * 64;
    Q[base + i]      =  q1 * c + q2 * sn;
    Q[base + i + 32] = -q1 * sn + q2 * c;
    K[base + i]      =  k1 * c + k2 * sn;
    K[base + i + 32] = -k1 * sn + k2 * c;
    for (int j = tid; j < 512; j += 256) {
        int hh = j >> 6, dd = j & 63;
        V[((size_t)(b * BH + hh) * SEQ + s) * 64 + dd] = row[1024 + j];
    }
}

// attention; output written as hi/lo half planes for the O-projection GEMM.
__global__ __launch_bounds__(128) void attn_k(const float* __restrict__ Q,
                                              const float* __restrict__ K,
                                              const float* __restrict__ V,
                                              __half* __restrict__ Oh,
                                              __half* __restrict__ Ol,
                                              const int* __restrict__ doc,
                                              int SEQ, int maskmode) {
    __shared__ float sq[64];
    __shared__ float sp[2048];
    __shared__ float red[128];
    int q = blockIdx.x;
    int bh = blockIdx.y;
    int b = bh / BH, h = bh % BH;
    int tid = threadIdx.x;
    const float* Qr = Q + ((size_t)bh * SEQ + q) * 64;
    if (tid < 64) sq[tid] = Qr[tid];
    __syncthreads();

    int kend = SEQ;
    int mydoc = 0;
    if (maskmode == 1) {
        kend = ((q >> 6) + 1) << 6;
        mydoc = doc[b * SEQ + q];
    }
    float m = -1e30f;
    for (int k = tid; k < kend; k += 128) {
        float s = -1e30f;
        bool ok = (maskmode == 0) || (doc[b * SEQ + k] == mydoc);
        if (ok) {
            const float4* kr = (const float4*)(K + ((size_t)bh * SEQ + k) * 64);
            const float4* qr = (const float4*)sq;
            float a = 0.f;
#pragma unroll
            for (int i = 0; i < 16; i++) {
                float4 kv = kr[i], qv = qr[i];
                a += kv.x * qv.x + kv.y * qv.y + kv.z * qv.z + kv.w * qv.w;
            }
            s = a * 0.125f;
        }
        sp[k] = s;
        m = fmaxf(m, s);
    }
    m = bmax128(m, red);

    float l = 0.f;
    for (int k = tid; k < kend; k += 128) {
        float e = expf(sp[k] - m);
        sp[k] = e;
        l += e;
    }
    l = bsum128(l, red);

    int d = tid & 63, half = tid >> 6;
    float acc = 0.f;
    for (int k = half; k < kend; k += 2)
        acc += sp[k] * V[((size_t)bh * SEQ + k) * 64 + d];
    red[tid] = acc;
    __syncthreads();
    if (tid < 64) {
        float o = (red[tid] + red[tid + 64]) / l;
        size_t idx = (size_t)(b * SEQ + q) * DMODEL + h * 64 + tid;
        __half hh, ll;
        split_h(o, hh, ll);
        Oh[idx] = hh;
        Ol[idx] = ll;
    }
}

__global__ void silu_k(const float* __restrict__ hbuf, __half* __restrict__ ah,
                       __half* __restrict__ al, int n) {
    int i = blockIdx.x * blockDim.x + threadIdx.x;
    if (i >= n) return;
    int t = i >> 10, j = i & 1023;
    float a = hbuf[(size_t)t * 2048 + j];
    float b = hbuf[(size_t)t * 2048 + 1024 + j];
    __half h, l;
    split_h((a / (1.0f + expf(-a))) * b, h, l);
    ah[i] = h;
    al[i] = l;
}

__global__ void build_xr_k(const float* __restrict__ x, const float* __restrict__ rt,
                           float* __restrict__ xr) {
    int i = blockIdx.x * blockDim.x + threadIdx.x;
    if (i >= NTOK_RTR * DMODEL) return;
    int blk = i / (SRTR * DMODEL);
    int rem = i % (SRTR * DMODEL);
    int t = rem / DMODEL, dd = rem % DMODEL;
    xr[i] = (t < 64) ? x[(size_t)(blk * 64 + t) * DMODEL + dd]
                     : rt[(size_t)(t - 64) * DMODEL + dd];
}

__global__ void gather_rows_k(const float* __restrict__ xr, __half* __restrict__ rh,
                              __half* __restrict__ rl) {
    int i = blockIdx.x * blockDim.x + threadIdx.x;
    if (i >= 512 * DMODEL) return;
    int row = i / DMODEL, dd = i % DMODEL;
    int blk = row >> 3, r = row & 7;
    __half h, l;
    split_h(xr[((size_t)blk * SRTR + 64 + r) * DMODEL + dd], h, l);
    rh[i] = h;
    rl[i] = l;
}

__global__ void knorm_k(const float* __restrict__ kr, const float* __restrict__ kg,
                        float* __restrict__ knr, float* __restrict__ kng) {
    int tid = threadIdx.x;
    int which = tid >> 9;
    int idx = tid & 511;
    int g = idx >> 4, e = idx & 15;
    const float* src = which ? kg : kr;
    const float* col = src + (size_t)g * 128 * 16 + e;
    float s = 0.f;
    for (int d = 0; d < 128; d++) { float v = col[d * 16]; s += v * v; }
    float n = fmaxf(sqrtf(s), 1e-12f);
    if (which) kng[idx] = n; else knr[idx] = n;
}

__global__ void logits_k(const float* __restrict__ outp,
                         const float* __restrict__ keys_r, const float* __restrict__ keys_g,
                         const float* __restrict__ knr, const float* __restrict__ kng,
                         float* __restrict__ rl, float* __restrict__ gl) {
    __shared__ float vr[128], vg[128], red[128];
    int g = blockIdx.x >> 6, bb = blockIdx.x & 63;
    int b = bb >> 5, l = bb & 31;
    int srcl = (l + 31) & 31;
    int r = g >> 2;
    const float* row = outp + (size_t)((b * 32 + srcl) * 8 + r) * 256;
    int tid = threadIdx.x;
    vr[tid] = row[tid];
    vg[tid] = row[128 + tid];
    float nr2 = bsum128(vr[tid] * vr[tid], red);
    float ng2 = bsum128(vg[tid] * vg[tid], red);
    float inr = 1.0f / fmaxf(sqrtf(nr2), 1e-12f);
    float ing = 1.0f / fmaxf(sqrtf(ng2), 1e-12f);
    if (tid < 16) {
        int e = tid;
        const float* kr = keys_r + (size_t)g * 128 * 16 + e;
        const float* kg = keys_g + (size_t)g * 128 * 16 + e;
        float dr = 0.f, dg = 0.f;
        for (int dd = 0; dd < 128; dd++) {
            dr += vr[dd] * kr[dd * 16];
            dg += vg[dd] * kg[dd * 16];
        }
        rl[(size_t)(g * 64 + bb) * 16 + e] = dr * inr / knr[g * 16 + e];
        gl[(size_t)(g * 64 + bb) * 16 + e] = dg * ing / kng[g * 16 + e];
    }
}

__global__ void topk_k(const float* __restrict__ rl, const float* __restrict__ gl,
                       float* __restrict__ out) {
    int t = blockIdx.x * blockDim.x + threadIdx.x;
    if (t >= 2048) return;
    const float* r = rl + (size_t)t * 16;
    const float* g = gl + (size_t)t * 16;
    int i1 = 0; float v1 = r[0];
    for (int e = 1; e < 16; e++) if (r[e] > v1) { v1 = r[e]; i1 = e; }
    int i2 = -1; float v2 = -1e30f;
    for (int e = 0; e < 16; e++) {
        if (e == i1) continue;
        if (r[e] > v2) { v2 = r[e]; i2 = e; }
    }
    out[(size_t)t * 2 + 0] = v1;
    out[(size_t)t * 2 + 1] = v2;
    out[4096 + (size_t)t * 2 + 0] = g[i1];
    out[4096 + (size_t)t * 2 + 1] = g[i2];
}

// ---------------- host orchestration ----------------
static void run_layer(float* cur, size_t qkvo, size_t oo, size_t upo, size_t dno,
                      const float* n1, const float* n2,
                      int ntok, int NB, int SEQ, int maskmode, const int* doc,
                      float* sb, __half* hb_) {
    float*  qkv = sb + OFF_QKV;
    float*  qb  = sb + OFF_Q;
    float*  kb  = sb + OFF_K;
    float*  vb  = sb + OFF_V;
    float*  hbuf = sb + OFF_H;
    __half* xnh = hb_ + HO_XNH; __half* xnl = hb_ + HO_XNL;
    __half* ath = hb_ + HO_ATTH; __half* atl = hb_ + HO_ATTL;
    __half* ach = hb_ + HO_ACTH; __half* acl = hb_ + HO_ACTL;
    __half* wh = hb_ + HO_WH;  __half* wl = hb_ + HO_WL;

    rmsnorm_k<<<ntok, 128>>>(cur, n1, xnh, xnl);
    sgemm_h3<<<dim3(1536 / 128, ntok / 128), 256>>>(xnh, xnl, wh + qkvo, wl + qkvo, qkv, ntok, 1536, 512, 0);
    split_rope_k<<<ntok, 256>>>(qkv, qb, kb, vb, SEQ);
    attn_k<<<dim3(SEQ, NB * BH), 128>>>(qb, kb, vb, ath, atl, doc, SEQ, maskmode);
    sgemm_h3<<<dim3(512 / 128, ntok / 128), 256>>>(ath, atl, wh + oo, wl + oo, cur, ntok, 512, 512, 1);
    rmsnorm_k<<<ntok, 128>>>(cur, n2, xnh, xnl);
    sgemm_h3<<<dim3(2048 / 128, ntok / 128), 256>>>(xnh, xnl, wh + upo, wl + upo, hbuf, ntok, 2048, 512, 0);
    silu_k<<<(ntok * 1024 + 255) / 256, 256>>>(hbuf, ach, acl, ntok * 1024);
    sgemm_h3<<<dim3(512 / 128, ntok / 128), 256>>>(ach, acl, wh + dno, wl + dno, cur, ntok, 512, 1024, 1);
}

extern "C" void kernel_launch(void* const* d_in, const int* in_sizes, int n_in,
                              void* d_out, int out_size) {
    const float* x_in   = (const float*)d_in[0];
    const int*   doc    = (const int*)d_in[1];
    const float* rt     = (const float*)d_in[2];
    const float* out_w  = (const float*)d_in[3];
    const float* keys_r = (const float*)d_in[4];
    const float* keys_g = (const float*)d_in[5];
    const float* e_qkv  = (const float*)d_in[6];
    const float* e_o    = (const float*)d_in[7];
    const float* e_up   = (const float*)d_in[8];
    const float* e_dn   = (const float*)d_in[9];
    const float* e_n1   = (const float*)d_in[10];
    const float* e_n2   = (const float*)d_in[11];
    const float* r_qkv  = (const float*)d_in[12];
    const float* r_o    = (const float*)d_in[13];
    const float* r_up   = (const float*)d_in[14];
    const float* r_dn   = (const float*)d_in[15];
    const float* r_n1   = (const float*)d_in[16];
    const float* r_n2   = (const float*)d_in[17];
    float* out = (float*)d_out;

    float* sb;
    cudaGetSymbolAddress((void**)&sb, g_s);
    __half* hb_;
    cudaGetSymbolAddress((void**)&hb_, g_h);

    float* xbuf = sb + OFF_X;
    float* xr   = sb + OFF_XR;
    float* outp = sb + OFF_OUT;
    float* knr  = sb + OFF_KNR;
    float* kng  = sb + OFF_KNG;
    float* rl   = sb + OFF_RL;
    float* gl   = sb + OFF_GL;
    __half* wh = hb_ + HO_WH;
    __half* wl = hb_ + HO_WL;
    __half* rowsh = hb_ + HO_ROWSH;
    __half* rowsl = hb_ + HO_ROWSL;

    // pre-split all weights, transposed to [N][K]
    for (int i = 0; i < 4; i++) {
        wsplitT_k<<<dim3(1536 / 32, 512 / 32), dim3(32, 8)>>>(
            e_qkv + (size_t)i * 512 * 1536, wh + WO_EQ + (size_t)i * 786432,
            wl + WO_EQ + (size_t)i * 786432, 512, 1536);
        wsplitT_k<<<dim3(512 / 32, 512 / 32), dim3(32, 8)>>>(
            e_o + (size_t)i * 512 * 512, wh + WO_EO + (size_t)i * 262144,
            wl + WO_EO + (size_t)i * 262144, 512, 512);
        wsplitT_k<<<dim3(2048 / 32, 512 / 32), dim3(32, 8)>>>(
            e_up + (size_t)i * 512 * 2048, wh + WO_EU + (size_t)i * 1048576,
            wl + WO_EU + (size_t)i * 1048576, 512, 2048);
        wsplitT_k<<<dim3(512 / 32, 1024 / 32), dim3(32, 8)>>>(
            e_dn + (size_t)i * 1024 * 512, wh + WO_ED + (size_t)i * 524288,
            wl + WO_ED + (size_t)i * 524288, 1024, 512);
    }
    for (int i = 0; i < 2; i++) {
        wsplitT_k<<<dim3(1536 / 32, 512 / 32), dim3(32, 8)>>>(
            r_qkv + (size_t)i * 512 * 1536, wh + WO_RQ + (size_t)i * 786432,
            wl + WO_RQ + (size_t)i * 786432, 512, 1536);
        wsplitT_k<<<dim3(512 / 32, 512 / 32), dim3(32, 8)>>>(
            r_o + (size_t)i * 512 * 512, wh + WO_RO + (size_t)i * 262144,
            wl + WO_RO + (size_t)i * 262144, 512, 512);
        wsplitT_k<<<dim3(2048 / 32, 512 / 32), dim3(32, 8)>>>(
            r_up + (size_t)i * 512 * 2048, wh + WO_RU + (size_t)i * 1048576,
            wl + WO_RU + (size_t)i * 1048576, 512, 2048);
        wsplitT_k<<<dim3(512 / 32, 1024 / 32), dim3(32, 8)>>>(
            r_dn + (size_t)i * 1024 * 512, wh + WO_RD + (size_t)i * 524288,
            wl + WO_RD + (size_t)i * 524288, 1024, 512);
    }
    wsplitT_k<<<dim3(256 / 32, 512 / 32), dim3(32, 8)>>>(out_w, wh + WO_OUT, wl + WO_OUT, 512, 256);

    copy_k<<<(NTOK_ENC * DMODEL + 255) / 256, 256>>>(x_in, xbuf, NTOK_ENC * DMODEL);

    for (int i = 0; i < 4; i++) {
        run_layer(xbuf,
                  WO_EQ + (size_t)i * 786432,
                  WO_EO + (size_t)i * 262144,
                  WO_EU + (size_t)i * 1048576,
                  WO_ED + (size_t)i * 524288,
                  e_n1 + (size_t)i * 512, e_n2 + (size_t)i * 512,
                  NTOK_ENC, 2, SENC, 1, doc, sb, hb_);
    }

    build_xr_k<<<(NTOK_RTR * DMODEL + 255) / 256, 256>>>(xbuf, rt, xr);

    for (int i = 0; i < 2; i++) {
        run_layer(xr,
                  WO_RQ + (size_t)i * 786432,
                  WO_RO + (size_t)i * 262144,
                  WO_RU + (size_t)i * 1048576,
                  WO_RD + (size_t)i * 524288,
                  r_n1 + (size_t)i * 512, r_n2 + (size_t)i * 512,
                  NTOK_RTR, 64, SRTR, 0, nullptr, sb, hb_);
    }

    gather_rows_k<<<(512 * DMODEL + 255) / 256, 256>>>(xr, rowsh, rowsl);
    sgemm_h3<<<dim3(256 / 128, 512 / 128), 256>>>(rowsh, rowsl, wh + WO_OUT, wl + WO_OUT, outp, 512, 256, 512, 0);

    knorm_k<<<1, 1024>>>(keys_r, keys_g, knr, kng);
    logits_k<<<32 * 64, 128>>>(outp, keys_r, keys_g, knr, kng, rl, gl);
    topk_k<<<16, 128>>>(rl, gl, out);
}

// round 7
// speedup vs baseline: 2.3544x; 1.9272x over previous
#include <cuda_runtime.h>
#include <cuda_fp16.h>
#include <math.h>
#include <stdint.h>

// Model constants
#define BH      8
#define HDIM    64
#define DMODEL  512
#define SENC    2048
#define SRTR    72
#define NTOK_ENC 4096
#define NTOK_RTR 4608
#define FFH     1024

// ---- fp32 scratch (float offsets) ----
#define OFF_QKV   0ull                 // 4608*1536
#define OFF_Q     7077888ull
#define OFF_K     9437184ull
#define OFF_V     11796480ull
#define OFF_H     14155776ull          // 4608*2048
#define OFF_X     23592960ull
#define OFF_XR    25952256ull
#define OFF_OUT   28311552ull          // 512*256
#define OFF_KNR   28442624ull
#define OFF_KNG   28443136ull
#define OFF_RL    28443648ull
#define OFF_GL    28476416ull
#define SCRATCH_FLOATS 28509184ull
__device__ float g_s[SCRATCH_FLOATS];

// ---- fp16 scratch (half offsets) ----
#define HO_XNH   0ull                  // 4608*512
#define HO_XNL   2359296ull
#define HO_ATTH  4718592ull
#define HO_ATTL  7077888ull
#define HO_ACTH  9437184ull            // 4608*1024
#define HO_ACTL  14155776ull
#define HO_ROWSH 18874368ull           // 512*512
#define HO_ROWSL 19136512ull
#define HO_WH    19398656ull           // all weights (transposed), 15859712 halves
#define HO_WL    35258368ull
#define SCRATCH_HALVES 51118080ull
__device__ __half g_h[SCRATCH_HALVES];

// weight-plane sub-offsets (halves)
#define WO_EQ   0ull         // 4 x [1536][512]
#define WO_EO   3145728ull   // 4 x [512][512]
#define WO_EU   4194304ull   // 4 x [2048][512]
#define WO_ED   8388608ull   // 4 x [512][1024]
#define WO_RQ   10485760ull
#define WO_RO   12058624ull
#define WO_RU   12582912ull
#define WO_RD   14680064ull
#define WO_OUT  15728640ull  // [256][512]

// ---------------- helpers ----------------
__device__ __forceinline__ float bsum128(float v, volatile float* red) {
    int tid = threadIdx.x;
    red[tid] = v;
    for (int off = 64; off >= 1; off >>= 1) {
        __syncthreads();
        if (tid < off) red[tid] += red[tid + off];
    }
    __syncthreads();
    float r = red[0];
    __syncthreads();
    return r;
}

__device__ __forceinline__ float bmax128(float v, volatile float* red) {
    int tid = threadIdx.x;
    red[tid] = v;
    for (int off = 64; off >= 1; off >>= 1) {
        __syncthreads();
        if (tid < off) red[tid] = fmaxf(red[tid], red[tid + off]);
    }
    __syncthreads();
    float r = red[0];
    __syncthreads();
    return r;
}

// fp32 -> fp16 hi + fp16 lo
__device__ __forceinline__ void split_h(float v, __half& hi, __half& lo) {
    hi = __float2half_rn(v);
    lo = __float2half_rn(v - __half2float(hi));
}

__device__ __forceinline__ void mma16816(float* c, const uint32_t* a, const uint32_t* b) {
    asm volatile(
        "mma.sync.aligned.m16n8k16.row.col.f32.f16.f16.f32 "
        "{%0,%1,%2,%3}, {%4,%5,%6,%7}, {%8,%9}, {%0,%1,%2,%3};"
        : "+f"(c[0]), "+f"(c[1]), "+f"(c[2]), "+f"(c[3])
        : "r"(a[0]), "r"(a[1]), "r"(a[2]), "r"(a[3]), "r"(b[0]), "r"(b[1]));
}

// ---------------- kernels ----------------
__global__ void copy_k(const float* __restrict__ src, float* __restrict__ dst, int n) {
    int i = blockIdx.x * blockDim.x + threadIdx.x;
    if (i < n) dst[i] = src[i];
}

// transpose + split: w[K][N] fp32 -> hT[N][K], lT[N][K] halves. grid(N/32,K/32) block(32,8)
__global__ void wsplitT_k(const float* __restrict__ w, __half* __restrict__ hT,
                          __half* __restrict__ lT, int K, int N) {
    __shared__ float t[32][33];
    int n0 = blockIdx.x * 32, k0 = blockIdx.y * 32;
    int tx = threadIdx.x, ty = threadIdx.y;
    for (int i = ty; i < 32; i += 8)
        t[i][tx] = w[(size_t)(k0 + i) * N + n0 + tx];
    __syncthreads();
    for (int i = ty; i < 32; i += 8) {
        float v = t[tx][i];                       // = w[k0+tx][n0+i]
        __half h, l;
        split_h(v, h, l);
        hT[(size_t)(n0 + i) * K + k0 + tx] = h;
        lT[(size_t)(n0 + i) * K + k0 + tx] = l;
    }
}

// rmsnorm -> hi/lo half planes. One block (128 thr) per token.
__global__ void rmsnorm_k(const float* __restrict__ x, const float* __restrict__ w,
                          __half* __restrict__ yh, __half* __restrict__ yl) {
    __shared__ float red[128];
    size_t row = (size_t)blockIdx.x * DMODEL;
    int tid = threadIdx.x;
    float ss = 0.f;
    for (int i = tid; i < DMODEL; i += 128) {
        float v = x[row + i];
        ss += v * v;
    }
    float tot = bsum128(ss, red);
    float scale = rsqrtf(tot / (float)DMODEL + 1e-6f);
    for (int i = tid; i < DMODEL; i += 128) {
        __half h, l;
        split_h(x[row + i] * scale * w[i], h, l);
        yh[row + i] = h;
        yl[row + i] = l;
    }
}

// ---- 3xFP16 split GEMM on tensor cores ----
__global__ __launch_bounds__(256) void sgemm_h3(const __half* __restrict__ Ah,
                                                const __half* __restrict__ Al,
                                                const __half* __restrict__ BTh,
                                                const __half* __restrict__ BTl,
                                                float* __restrict__ C,
                                                int M, int N, int K, int accum) {
    __shared__ __align__(16) __half As[2][2][128][24];   // [buf][plane][row][k]
    __shared__ __align__(16) __half Bs[2][2][128][24];   // [buf][plane][n][k]
    int tid = threadIdx.x;
    int lane = tid & 31, warp = tid >> 5;
    int wm = warp >> 2, wn = warp & 3;
    int grp = lane >> 2, qid = lane & 3;
    int bm = blockIdx.y * 128, bn = blockIdx.x * 128;

    float acc[4][4][4];
#pragma unroll
    for (int i = 0; i < 4; i++)
#pragma unroll
        for (int j = 0; j < 4; j++)
#pragma unroll
            for (int t = 0; t < 4; t++) acc[i][j][t] = 0.f;

    int lrow = tid >> 1, lseg = (tid & 1) * 8;
    uint4 pah, pal, pbh, pbl;

#define LOAD(k0)                                                                   \
    {                                                                              \
        pah = *(const uint4*)(Ah + (size_t)(bm + lrow) * K + (k0) + lseg);         \
        pal = *(const uint4*)(Al + (size_t)(bm + lrow) * K + (k0) + lseg);         \
        pbh = *(const uint4*)(BTh + (size_t)(bn + lrow) * K + (k0) + lseg);        \
        pbl = *(const uint4*)(BTl + (size_t)(bn + lrow) * K + (k0) + lseg);        \
    }
#define STORE(buf)                                                                 \
    {                                                                              \
        *(uint4*)&As[buf][0][lrow][lseg] = pah;                                    \
        *(uint4*)&As[buf][1][lrow][lseg] = pal;                                    \
        *(uint4*)&Bs[buf][0][lrow][lseg] = pbh;                                    \
        *(uint4*)&Bs[buf][1][lrow][lseg] = pbl;                                    \
    }

    LOAD(0);
    STORE(0);
    __syncthreads();

    int nk = K >> 4;
    for (int kt = 0; kt < nk; kt++) {
        int buf = kt & 1;
        if (kt + 1 < nk) LOAD((kt + 1) << 4);

        uint32_t ah[4][4], al[4][4], bh[4][2], bl[4][2];
#pragma unroll
        for (int mt = 0; mt < 4; mt++) {
            int r0 = wm * 64 + mt * 16 + grp;
            ah[mt][0] = *(const uint32_t*)&As[buf][0][r0][2 * qid];
            ah[mt][1] = *(const uint32_t*)&As[buf][0][r0 + 8][2 * qid];
            ah[mt][2] = *(const uint32_t*)&As[buf][0][r0][2 * qid + 8];
            ah[mt][3] = *(const uint32_t*)&As[buf][0][r0 + 8][2 * qid + 8];
            al[mt][0] = *(const uint32_t*)&As[buf][1][r0][2 * qid];
            al[mt][1] = *(const uint32_t*)&As[buf][1][r0 + 8][2 * qid];
            al[mt][2] = *(const uint32_t*)&As[buf][1][r0][2 * qid + 8];
            al[mt][3] = *(const uint32_t*)&As[buf][1][r0 + 8][2 * qid + 8];
        }
#pragma unroll
        for (int nt = 0; nt < 4; nt++) {
            int c0 = wn * 32 + nt * 8 + grp;
            bh[nt][0] = *(const uint32_t*)&Bs[buf][0][c0][2 * qid];
            bh[nt][1] = *(const uint32_t*)&Bs[buf][0][c0][2 * qid + 8];
            bl[nt][0] = *(const uint32_t*)&Bs[buf][1][c0][2 * qid];
            bl[nt][1] = *(const uint32_t*)&Bs[buf][1][c0][2 * qid + 8];
        }
#pragma unroll
        for (int mt = 0; mt < 4; mt++)
#pragma unroll
            for (int nt = 0; nt < 4; nt++) {
                mma16816(acc[mt][nt], al[mt], bh[nt]);
                mma16816(acc[mt][nt], ah[mt], bl[nt]);
                mma16816(acc[mt][nt], ah[mt], bh[nt]);
            }
        if (kt + 1 < nk) STORE(buf ^ 1);
        __syncthreads();
    }

#pragma unroll
    for (int mt = 0; mt < 4; mt++) {
#pragma unroll
        for (int nt = 0; nt < 4; nt++) {
            int r0 = bm + wm * 64 + mt * 16 + grp;
            int c0 = bn + wn * 32 + nt * 8 + 2 * qid;
            size_t i00 = (size_t)r0 * N + c0;
            size_t i10 = (size_t)(r0 + 8) * N + c0;
            if (accum) {
                C[i00]     += acc[mt][nt][0];
                C[i00 + 1] += acc[mt][nt][1];
                C[i10]     += acc[mt][nt][2];
                C[i10 + 1] += acc[mt][nt][3];
            } else {
                C[i00]     = acc[mt][nt][0];
                C[i00 + 1] = acc[mt][nt][1];
                C[i10]     = acc[mt][nt][2];
                C[i10 + 1] = acc[mt][nt][3];
            }
        }
    }
#undef LOAD
#undef STORE
}

// qkv row -> q/k (RoPE) and v, layout [bh][SEQ][64]. grid=ntok, block=256
__global__ void split_rope_k(const float* __restrict__ qkv,
                             float* __restrict__ Q, float* __restrict__ K,
                             float* __restrict__ V, int SEQ) {
    int tok = blockIdx.x;
    int b = tok / SEQ, s = tok % SEQ;
    const float* row = qkv + (size_t)tok * 1536;
    int tid = threadIdx.x;
    int h = tid >> 5, i = tid & 31;
    float q1 = row[h * 64 + i], q2 = row[h * 64 + i + 32];
    float k1 = row[512 + h * 64 + i], k2 = row[512 + h * 64 + i + 32];
    float inv = powf(1e-4f, (float)i * (1.0f / 32.0f));
    float ang = (float)s * inv;
    float c = cosf(ang), sn = sinf(ang);
    size_t base = ((size_t)(b * BH + h) * SEQ + s) * 64;
    Q[base + i]      =  q1 * c + q2 * sn;
    Q[base + i + 32] = -q1 * sn + q2 * c;
    K[base + i]      =  k1 * c + k2 * sn;
    K[base + i + 32] = -k1 * sn + k2 * c;
    for (int j = tid; j < 512; j += 256) {
        int hh = j >> 6, dd = j & 63;
        V[((size_t)(b * BH + hh) * SEQ + s) * 64 + dd] = row[1024 + j];
    }
}

// ---- tiled flash attention for encoder (block-causal at 64 + doc mask) ----
// grid (SEQ/64, B*BH), block 128. dynamic smem 69,632 B.
// Thread: qg = tid>>4 -> 8 q rows; kg = tid&15 -> 4 k cols (scores) / 4 dims (PV).
__global__ __launch_bounds__(128) void attn_tile_k(const float* __restrict__ Q,
                                                   const float* __restrict__ K,
                                                   const float* __restrict__ V,
                                                   __half* __restrict__ Oh,
                                                   __half* __restrict__ Ol,
                                                   const int* __restrict__ doc,
                                                   int SEQ) {
    extern __shared__ float sm[];
    float* Qs = sm;            // [64][68]
    float* Ks = sm + 4352;
    float* Vs = sm + 8704;
    float* Ps = sm + 13056;

    int qb = blockIdx.x, bh = blockIdx.y;
    int b = bh >> 3, h = bh & 7;
    int tid = threadIdx.x;
    int qg = tid >> 4, kg = tid & 15;
    int q0 = qg * 8, k0 = kg * 4, d0 = kg * 4;

    const float* Qb = Q + ((size_t)bh * SEQ + qb * 64) * 64;
    const float* Kb = K + (size_t)bh * SEQ * 64;
    const float* Vb = V + (size_t)bh * SEQ * 64;

    // load Q tile (linear, coalesced)
    {
        const float4* src = (const float4*)Qb;
#pragma unroll
        for (int i = 0; i < 8; i++) {
            int fi = tid + 128 * i;
            int r = fi >> 4, c = fi & 15;
            *(float4*)(Qs + r * 68 + c * 4) = src[fi];
        }
    }
    int dqr[8];
#pragma unroll
    for (int j = 0; j < 8; j++) dqr[j] = doc[b * SEQ + qb * 64 + q0 + j];

    float4 o4[8];
    float mrow[8], lrow[8];
#pragma unroll
    for (int j = 0; j < 8; j++) {
        o4[j] = make_float4(0.f, 0.f, 0.f, 0.f);
        mrow[j] = -1e30f;
        lrow[j] = 0.f;
    }

    for (int kt = 0; kt <= qb; kt++) {
        int kbase = kt * 64;
        __syncthreads();          // previous tile's PV done before overwrite
        {
            const float4* ksrc = (const float4*)(Kb + kbase * 64);
            const float4* vsrc = (const float4*)(Vb + kbase * 64);
#pragma unroll
            for (int i = 0; i < 8; i++) {
                int fi = tid + 128 * i;
                int r = fi >> 4, c = fi & 15;
                *(float4*)(Ks + r * 68 + c * 4) = ksrc[fi];
                *(float4*)(Vs + r * 68 + c * 4) = vsrc[fi];
            }
        }
        __syncthreads();

        // scores
        float s[8][4];
#pragma unroll
        for (int j = 0; j < 8; j++)
#pragma unroll
            for (int i = 0; i < 4; i++) s[j][i] = 0.f;
#pragma unroll 4
        for (int dv = 0; dv < 16; dv++) {
            float4 kv[4];
#pragma unroll
            for (int i = 0; i < 4; i++) kv[i] = *(const float4*)(Ks + (k0 + i) * 68 + dv * 4);
#pragma unroll
            for (int j = 0; j < 8; j++) {
                float4 qv = *(const float4*)(Qs + (q0 + j) * 68 + dv * 4);
#pragma unroll
                for (int i = 0; i < 4; i++)
                    s[j][i] += qv.x * kv[i].x + qv.y * kv[i].y + qv.z * kv[i].z + qv.w * kv[i].w;
            }
        }
        int dkr[4];
#pragma unroll
        for (int i = 0; i < 4; i++) dkr[i] = doc[b * SEQ + kbase + k0 + i];
#pragma unroll
        for (int j = 0; j < 8; j++)
#pragma unroll
            for (int i = 0; i < 4; i++)
                s[j][i] = (dkr[i] == dqr[j]) ? s[j][i] * 0.125f : -6e30f;

        // online softmax; 16 lanes share a row (xor offsets < 16 stay in group)
#pragma unroll
        for (int j = 0; j < 8; j++) {
            float tm = fmaxf(fmaxf(s[j][0], s[j][1]), fmaxf(s[j][2], s[j][3]));
#pragma unroll
            for (int off = 1; off < 16; off <<= 1)
                tm = fmaxf(tm, __shfl_xor_sync(0xffffffffu, tm, off));
            float mnew = fmaxf(mrow[j], tm);
            float r = __expf(mrow[j] - mnew);
            float4 p;
            p.x = __expf(s[j][0] - mnew);
            p.y = __expf(s[j][1] - mnew);
            p.z = __expf(s[j][2] - mnew);
            p.w = __expf(s[j][3] - mnew);
            float ps = p.x + p.y + p.z + p.w;
#pragma unroll
            for (int off = 1; off < 16; off <<= 1)
                ps += __shfl_xor_sync(0xffffffffu, ps, off);
            lrow[j] = lrow[j] * r + ps;
            mrow[j] = mnew;
            o4[j].x *= r; o4[j].y *= r; o4[j].z *= r; o4[j].w *= r;
            *(float4*)(Ps + (q0 + j) * 68 + k0) = p;
        }
        __syncwarp();

        // PV
#pragma unroll 4
        for (int kc = 0; kc < 16; kc++) {
            float4 vv[4];
#pragma unroll
            for (int i = 0; i < 4; i++) vv[i] = *(const float4*)(Vs + (kc * 4 + i) * 68 + d0);
#pragma unroll
            for (int j = 0; j < 8; j++) {
                float4 p = *(const float4*)(Ps + (q0 + j) * 68 + kc * 4);
                o4[j].x += p.x * vv[0].x + p.y * vv[1].x + p.z * vv[2].x + p.w * vv[3].x;
                o4[j].y += p.x * vv[0].y + p.y * vv[1].y + p.z * vv[2].y + p.w * vv[3].y;
                o4[j].z += p.x * vv[0].z + p.y * vv[1].z + p.z * vv[2].z + p.w * vv[3].z;
                o4[j].w += p.x * vv[0].w + p.y * vv[1].w + p.z * vv[2].w + p.w * vv[3].w;
            }
        }
    }

    // epilogue: normalize + split-write
#pragma unroll
    for (int j = 0; j < 8; j++) {
        float inv = 1.0f / lrow[j];
        int row = qb * 64 + q0 + j;
        size_t base = (size_t)(b * SEQ + row) * DMODEL + h * 64 + d0;
        float vals[4] = {o4[j].x * inv, o4[j].y * inv, o4[j].z * inv, o4[j].w * inv};
#pragma unroll
        for (int i = 0; i < 4; i++) {
            __half hh, ll;
            split_h(vals[i], hh, ll);
            Oh[base + i] = hh;
            Ol[base + i] = ll;
        }
    }
}

// router attention (small, full attention within 72 tokens)
__global__ __launch_bounds__(128) void attn_k(const float* __restrict__ Q,
                                              const float* __restrict__ K,
                                              const float* __restrict__ V,
                                              __half* __restrict__ Oh,
                                              __half* __restrict__ Ol,
                                              int SEQ) {
    __shared__ float sq[64];
    __shared__ float sp[128];
    __shared__ float red[128];
    int q = blockIdx.x;
    int bh = blockIdx.y;
    int b = bh / BH, h = bh % BH;
    int tid = threadIdx.x;
    const float* Qr = Q + ((size_t)bh * SEQ + q) * 64;
    if (tid < 64) sq[tid] = Qr[tid];
    __syncthreads();

    int kend = SEQ;
    float m = -1e30f;
    for (int k = tid; k < kend; k += 128) {
        const float4* kr = (const float4*)(K + ((size_t)bh * SEQ + k) * 64);
        const float4* qr = (const float4*)sq;
        float a = 0.f;
#pragma unroll
        for (int i = 0; i < 16; i++) {
            float4 kv = kr[i], qv = qr[i];
            a += kv.x * qv.x + kv.y * qv.y + kv.z * qv.z + kv.w * qv.w;
        }
        sp[k] = a * 0.125f;
        m = fmaxf(m, a * 0.125f);
    }
    m = bmax128(m, red);

    float l = 0.f;
    for (int k = tid; k < kend; k += 128) {
        float e = __expf(sp[k] - m);
        sp[k] = e;
        l += e;
    }
    l = bsum128(l, red);

    int d = tid & 63, half = tid >> 6;
    float acc = 0.f;
    for (int k = half; k < kend; k += 2)
        acc += sp[k] * V[((size_t)bh * SEQ + k) * 64 + d];
    red[tid] = acc;
    __syncthreads();
    if (tid < 64) {
        float o = (red[tid] + red[tid + 64]) / l;
        size_t idx = (size_t)(b * SEQ + q) * DMODEL + h * 64 + tid;
        __half hh, ll;
        split_h(o, hh, ll);
        Oh[idx] = hh;
        Ol[idx] = ll;
    }
}

__global__ void silu_k(const float* __restrict__ hbuf, __half* __restrict__ ah,
                       __half* __restrict__ al, int n) {
    int i = blockIdx.x * blockDim.x + threadIdx.x;
    if (i >= n) return;
    int t = i >> 10, j = i & 1023;
    float a = hbuf[(size_t)t * 2048 + j];
    float b = hbuf[(size_t)t * 2048 + 1024 + j];
    __half h, l;
    split_h((a / (1.0f + __expf(-a))) * b, h, l);
    ah[i] = h;
    al[i] = l;
}

__global__ void build_xr_k(const float* __restrict__ x, const float* __restrict__ rt,
                           float* __restrict__ xr) {
    int i = blockIdx.x * blockDim.x + threadIdx.x;
    if (i >= NTOK_RTR * DMODEL) return;
    int blk = i / (SRTR * DMODEL);
    int rem = i % (SRTR * DMODEL);
    int t = rem / DMODEL, dd = rem % DMODEL;
    xr[i] = (t < 64) ? x[(size_t)(blk * 64 + t) * DMODEL + dd]
                     : rt[(size_t)(t - 64) * DMODEL + dd];
}

__global__ void gather_rows_k(const float* __restrict__ xr, __half* __restrict__ rh,
                              __half* __restrict__ rl) {
    int i = blockIdx.x * blockDim.x + threadIdx.x;
    if (i >= 512 * DMODEL) return;
    int row = i / DMODEL, dd = i % DMODEL;
    int blk = row >> 3, r = row & 7;
    __half h, l;
    split_h(xr[((size_t)blk * SRTR + 64 + r) * DMODEL + dd], h, l);
    rh[i] = h;
    rl[i] = l;
}

__global__ void knorm_k(const float* __restrict__ kr, const float* __restrict__ kg,
                        float* __restrict__ knr, float* __restrict__ kng) {
    int tid = threadIdx.x;
    int which = tid >> 9;
    int idx = tid & 511;
    int g = idx >> 4, e = idx & 15;
    const float* src = which ? kg : kr;
    const float* col = src + (size_t)g * 128 * 16 + e;
    float s = 0.f;
    for (int d = 0; d < 128; d++) { float v = col[d * 16]; s += v * v; }
    float n = fmaxf(sqrtf(s), 1e-12f);
    if (which) kng[idx] = n; else knr[idx] = n;
}

__global__ void logits_k(const float* __restrict__ outp,
                         const float* __restrict__ keys_r, const float* __restrict__ keys_g,
                         const float* __restrict__ knr, const float* __restrict__ kng,
                         float* __restrict__ rl, float* __restrict__ gl) {
    __shared__ float vr[128], vg[128], red[128];
    int g = blockIdx.x >> 6, bb = blockIdx.x & 63;
    int b = bb >> 5, l = bb & 31;
    int srcl = (l + 31) & 31;
    int r = g >> 2;
    const float* row = outp + (size_t)((b * 32 + srcl) * 8 + r) * 256;
    int tid = threadIdx.x;
    vr[tid] = row[tid];
    vg[tid] = row[128 + tid];
    float nr2 = bsum128(vr[tid] * vr[tid], red);
    float ng2 = bsum128(vg[tid] * vg[tid], red);
    float inr = 1.0f / fmaxf(sqrtf(nr2), 1e-12f);
    float ing = 1.0f / fmaxf(sqrtf(ng2), 1e-12f);
    if (tid < 16) {
        int e = tid;
        const float* kr = keys_r + (size_t)g * 128 * 16 + e;
        const float* kg = keys_g + (size_t)g * 128 * 16 + e;
        float dr = 0.f, dg = 0.f;
        for (int dd = 0; dd < 128; dd++) {
            dr += vr[dd] * kr[dd * 16];
            dg += vg[dd] * kg[dd * 16];
        }
        rl[(size_t)(g * 64 + bb) * 16 + e] = dr * inr / knr[g * 16 + e];
        gl[(size_t)(g * 64 + bb) * 16 + e] = dg * ing / kng[g * 16 + e];
    }
}

__global__ void topk_k(const float* __restrict__ rl, const float* __restrict__ gl,
                       float* __restrict__ out) {
    int t = blockIdx.x * blockDim.x + threadIdx.x;
    if (t >= 2048) return;
    const float* r = rl + (size_t)t * 16;
    const float* g = gl + (size_t)t * 16;
    int i1 = 0; float v1 = r[0];
    for (int e = 1; e < 16; e++) if (r[e] > v1) { v1 = r[e]; i1 = e; }
    int i2 = -1; float v2 = -1e30f;
    for (int e = 0; e < 16; e++) {
        if (e == i1) continue;
        if (r[e] > v2) { v2 = r[e]; i2 = e; }
    }
    out[(size_t)t * 2 + 0] = v1;
    out[(size_t)t * 2 + 1] = v2;
    out[4096 + (size_t)t * 2 + 0] = g[i1];
    out[4096 + (size_t)t * 2 + 1] = g[i2];
}

// ---------------- host orchestration ----------------
#define ATTN_SMEM 69632

static void run_layer(float* cur, size_t qkvo, size_t oo, size_t upo, size_t dno,
                      const float* n1, const float* n2,
                      int ntok, int SEQ, int enc, const int* doc,
                      float* sb, __half* hb_) {
    float*  qkv = sb + OFF_QKV;
    float*  qb  = sb + OFF_Q;
    float*  kb  = sb + OFF_K;
    float*  vb  = sb + OFF_V;
    float*  hbuf = sb + OFF_H;
    __half* xnh = hb_ + HO_XNH; __half* xnl = hb_ + HO_XNL;
    __half* ath = hb_ + HO_ATTH; __half* atl = hb_ + HO_ATTL;
    __half* ach = hb_ + HO_ACTH; __half* acl = hb_ + HO_ACTL;
    __half* wh = hb_ + HO_WH;  __half* wl = hb_ + HO_WL;

    rmsnorm_k<<<ntok, 128>>>(cur, n1, xnh, xnl);
    sgemm_h3<<<dim3(1536 / 128, ntok / 128), 256>>>(xnh, xnl, wh + qkvo, wl + qkvo, qkv, ntok, 1536, 512, 0);
    split_rope_k<<<ntok, 256>>>(qkv, qb, kb, vb, SEQ);
    if (enc)
        attn_tile_k<<<dim3(SEQ / 64, (ntok / SEQ) * BH), 128, ATTN_SMEM>>>(qb, kb, vb, ath, atl, doc, SEQ);
    else
        attn_k<<<dim3(SEQ, (ntok / SEQ) * BH), 128>>>(qb, kb, vb, ath, atl, SEQ);
    sgemm_h3<<<dim3(512 / 128, ntok / 128), 256>>>(ath, atl, wh + oo, wl + oo, cur, ntok, 512, 512, 1);
    rmsnorm_k<<<ntok, 128>>>(cur, n2, xnh, xnl);
    sgemm_h3<<<dim3(2048 / 128, ntok / 128), 256>>>(xnh, xnl, wh + upo, wl + upo, hbuf, ntok, 2048, 512, 0);
    silu_k<<<(ntok * 1024 + 255) / 256, 256>>>(hbuf, ach, acl, ntok * 1024);
    sgemm_h3<<<dim3(512 / 128, ntok / 128), 256>>>(ach, acl, wh + dno, wl + dno, cur, ntok, 512, 1024, 1);
}

extern "C" void kernel_launch(void* const* d_in, const int* in_sizes, int n_in,
                              void* d_out, int out_size) {
    const float* x_in   = (const float*)d_in[0];
    const int*   doc    = (const int*)d_in[1];
    const float* rt     = (const float*)d_in[2];
    const float* out_w  = (const float*)d_in[3];
    const float* keys_r = (const float*)d_in[4];
    const float* keys_g = (const float*)d_in[5];
    const float* e_qkv  = (const float*)d_in[6];
    const float* e_o    = (const float*)d_in[7];
    const float* e_up   = (const float*)d_in[8];
    const float* e_dn   = (const float*)d_in[9];
    const float* e_n1   = (const float*)d_in[10];
    const float* e_n2   = (const float*)d_in[11];
    const float* r_qkv  = (const float*)d_in[12];
    const float* r_o    = (const float*)d_in[13];
    const float* r_up   = (const float*)d_in[14];
    const float* r_dn   = (const float*)d_in[15];
    const float* r_n1   = (const float*)d_in[16];
    const float* r_n2   = (const float*)d_in[17];
    float* out = (float*)d_out;

    static int smem_set = 0;
    if (!smem_set) {
        cudaFuncSetAttribute(attn_tile_k, cudaFuncAttributeMaxDynamicSharedMemorySize, ATTN_SMEM);
        smem_set = 1;
    }

    float* sb;
    cudaGetSymbolAddress((void**)&sb, g_s);
    __half* hb_;
    cudaGetSymbolAddress((void**)&hb_, g_h);

    float* xbuf = sb + OFF_X;
    float* xr   = sb + OFF_XR;
    float* outp = sb + OFF_OUT;
    float* knr  = sb + OFF_KNR;
    float* kng  = sb + OFF_KNG;
    float* rl   = sb + OFF_RL;
    float* gl   = sb + OFF_GL;
    __half* wh = hb_ + HO_WH;
    __half* wl = hb_ + HO_WL;
    __half* rowsh = hb_ + HO_ROWSH;
    __half* rowsl = hb_ + HO_ROWSL;

    // pre-split all weights, transposed to [N][K]
    for (int i = 0; i < 4; i++) {
        wsplitT_k<<<dim3(1536 / 32, 512 / 32), dim3(32, 8)>>>(
            e_qkv + (size_t)i * 512 * 1536, wh + WO_EQ + (size_t)i * 786432,
            wl + WO_EQ + (size_t)i * 786432, 512, 1536);
        wsplitT_k<<<dim3(512 / 32, 512 / 32), dim3(32, 8)>>>(
            e_o + (size_t)i * 512 * 512, wh + WO_EO + (size_t)i * 262144,
            wl + WO_EO + (size_t)i * 262144, 512, 512);
        wsplitT_k<<<dim3(2048 / 32, 512 / 32), dim3(32, 8)>>>(
            e_up + (size_t)i * 512 * 2048, wh + WO_EU + (size_t)i * 1048576,
            wl + WO_EU + (size_t)i * 1048576, 512, 2048);
        wsplitT_k<<<dim3(512 / 32, 1024 / 32), dim3(32, 8)>>>(
            e_dn + (size_t)i * 1024 * 512, wh + WO_ED + (size_t)i * 524288,
            wl + WO_ED + (size_t)i * 524288, 1024, 512);
    }
    for (int i = 0; i < 2; i++) {
        wsplitT_k<<<dim3(1536 / 32, 512 / 32), dim3(32, 8)>>>(
            r_qkv + (size_t)i * 512 * 1536, wh + WO_RQ + (size_t)i * 786432,
            wl + WO_RQ + (size_t)i * 786432, 512, 1536);
        wsplitT_k<<<dim3(512 / 32, 512 / 32), dim3(32, 8)>>>(
            r_o + (size_t)i * 512 * 512, wh + WO_RO + (size_t)i * 262144,
            wl + WO_RO + (size_t)i * 262144, 512, 512);
        wsplitT_k<<<dim3(2048 / 32, 512 / 32), dim3(32, 8)>>>(
            r_up + (size_t)i * 512 * 2048, wh + WO_RU + (size_t)i * 1048576,
            wl + WO_RU + (size_t)i * 1048576, 512, 2048);
        wsplitT_k<<<dim3(512 / 32, 1024 / 32), dim3(32, 8)>>>(
            r_dn + (size_t)i * 1024 * 512, wh + WO_RD + (size_t)i * 524288,
            wl + WO_RD + (size_t)i * 524288, 1024, 512);
    }
    wsplitT_k<<<dim3(256 / 32, 512 / 32), dim3(32, 8)>>>(out_w, wh + WO_OUT, wl + WO_OUT, 512, 256);

    copy_k<<<(NTOK_ENC * DMODEL + 255) / 256, 256>>>(x_in, xbuf, NTOK_ENC * DMODEL);

    for (int i = 0; i < 4; i++) {
        run_layer(xbuf,
                  WO_EQ + (size_t)i * 786432,
                  WO_EO + (size_t)i * 262144,
                  WO_EU + (size_t)i * 1048576,
                  WO_ED + (size_t)i * 524288,
                  e_n1 + (size_t)i * 512, e_n2 + (size_t)i * 512,
                  NTOK_ENC, SENC, 1, doc, sb, hb_);
    }

    build_xr_k<<<(NTOK_RTR * DMODEL + 255) / 256, 256>>>(xbuf, rt, xr);

    for (int i = 0; i < 2; i++) {
        run_layer(xr,
                  WO_RQ + (size_t)i * 786432,
                  WO_RO + (size_t)i * 262144,
                  WO_RU + (size_t)i * 1048576,
                  WO_RD + (size_t)i * 524288,
                  r_n1 + (size_t)i * 512, r_n2 + (size_t)i * 512,
                  NTOK_RTR, SRTR, 0, nullptr, sb, hb_);
    }

    gather_rows_k<<<(512 * DMODEL + 255) / 256, 256>>>(xr, rowsh, rowsl);
    sgemm_h3<<<dim3(256 / 128, 512 / 128), 256>>>(rowsh, rowsl, wh + WO_OUT, wl + WO_OUT, outp, 512, 256, 512, 0);

    knorm_k<<<1, 1024>>>(keys_r, keys_g, knr, kng);
    logits_k<<<32 * 64, 128>>>(outp, keys_r, keys_g, knr, kng, rl, gl);
    topk_k<<<16, 128>>>(rl, gl, out);
}

// round 8
// speedup vs baseline: 2.4613x; 1.0454x over previous
#include <cuda_runtime.h>
#include <cuda_fp16.h>
#include <math.h>
#include <stdint.h>

// Model constants
#define BH      8
#define HDIM    64
#define DMODEL  512
#define SENC    2048
#define SRTR    72
#define NTOK_ENC 4096
#define NTOK_RTR 4608
#define FFH     1024

// ---- fp32 scratch (float offsets) ----
#define OFF_QKV   0ull                 // 4608*1536
#define OFF_Q     7077888ull
#define OFF_K     9437184ull
#define OFF_V     11796480ull
#define OFF_H     14155776ull          // (mostly unused now)
#define OFF_X     23592960ull
#define OFF_XR    25952256ull
#define OFF_OUT   28311552ull          // 512*256
#define OFF_KNR   28442624ull
#define OFF_KNG   28443136ull
#define OFF_RL    28443648ull
#define OFF_GL    28476416ull
#define SCRATCH_FLOATS 28509184ull
__device__ float g_s[SCRATCH_FLOATS];

// ---- fp16 scratch (half offsets) ----
#define HO_XNH   0ull                  // 4608*512
#define HO_XNL   2359296ull
#define HO_ATTH  4718592ull
#define HO_ATTL  7077888ull
#define HO_ACTH  9437184ull            // 4608*1024
#define HO_ACTL  14155776ull
#define HO_ROWSH 18874368ull           // 512*512
#define HO_ROWSL 19136512ull
#define HO_WH    19398656ull           // all weights (transposed), 15859712 halves
#define HO_WL    35258368ull
#define SCRATCH_HALVES 51118080ull
__device__ __half g_h[SCRATCH_HALVES];

// weight-plane sub-offsets (halves)
#define WO_EQ   0ull         // 4 x [1536][512]
#define WO_EO   3145728ull   // 4 x [512][512]
#define WO_EU   4194304ull   // 4 x [2048][512] (interleaved h1/h2)
#define WO_ED   8388608ull   // 4 x [512][1024]
#define WO_RQ   10485760ull
#define WO_RO   12058624ull
#define WO_RU   12582912ull
#define WO_RD   14680064ull
#define WO_OUT  15728640ull  // [256][512]

// ---------------- helpers ----------------
__device__ __forceinline__ float bsum128(float v, volatile float* red) {
    int tid = threadIdx.x;
    red[tid] = v;
    for (int off = 64; off >= 1; off >>= 1) {
        __syncthreads();
        if (tid < off) red[tid] += red[tid + off];
    }
    __syncthreads();
    float r = red[0];
    __syncthreads();
    return r;
}

__device__ __forceinline__ float bmax128(float v, volatile float* red) {
    int tid = threadIdx.x;
    red[tid] = v;
    for (int off = 64; off >= 1; off >>= 1) {
        __syncthreads();
        if (tid < off) red[tid] = fmaxf(red[tid], red[tid + off]);
    }
    __syncthreads();
    float r = red[0];
    __syncthreads();
    return r;
}

// fp32 -> fp16 hi + fp16 lo
__device__ __forceinline__ void split_h(float v, __half& hi, __half& lo) {
    hi = __float2half_rn(v);
    lo = __float2half_rn(v - __half2float(hi));
}

__device__ __forceinline__ void mma16816(float* c, const uint32_t* a, const uint32_t* b) {
    asm volatile(
        "mma.sync.aligned.m16n8k16.row.col.f32.f16.f16.f32 "
        "{%0,%1,%2,%3}, {%4,%5,%6,%7}, {%8,%9}, {%0,%1,%2,%3};"
        : "+f"(c[0]), "+f"(c[1]), "+f"(c[2]), "+f"(c[3])
        : "r"(a[0]), "r"(a[1]), "r"(a[2]), "r"(a[3]), "r"(b[0]), "r"(b[1]));
}

__device__ __forceinline__ uint32_t sptr(const void* p) {
    return (uint32_t)__cvta_generic_to_shared(p);
}

__device__ __forceinline__ void ldsm4(uint32_t& r0, uint32_t& r1, uint32_t& r2,
                                      uint32_t& r3, uint32_t addr) {
    asm volatile("ldmatrix.sync.aligned.m8n8.x4.shared.b16 {%0,%1,%2,%3}, [%4];"
                 : "=r"(r0), "=r"(r1), "=r"(r2), "=r"(r3) : "r"(addr));
}

__device__ __forceinline__ void cpa16(uint32_t dst, const void* src) {
    asm volatile("cp.async.cg.shared.global [%0], [%1], 16;" :: "r"(dst), "l"(src));
}
__device__ __forceinline__ void cpa_commit() { asm volatile("cp.async.commit_group;"); }
__device__ __forceinline__ void cpa_wait0() { asm volatile("cp.async.wait_group 0;"); }

// ---------------- kernels ----------------
__global__ void copy_k(const float* __restrict__ src, float* __restrict__ dst, int n) {
    int i = blockIdx.x * blockDim.x + threadIdx.x;
    if (i < n) dst[i] = src[i];
}

// transpose + split: w[K][N] fp32 -> hT[N][K], lT[N][K] halves.
// ilv != 0: output row n sources col (n odd ? N/2 + n/2 : n/2)  (h1/h2 interleave)
__global__ void wsplitT_k(const float* __restrict__ w, __half* __restrict__ hT,
                          __half* __restrict__ lT, int K, int N, int ilv) {
    __shared__ float t[32][33];
    int n0 = blockIdx.x * 32, k0 = blockIdx.y * 32;
    int tx = threadIdx.x, ty = threadIdx.y;
    for (int i = ty; i < 32; i += 8) {
        int n = n0 + tx;
        int srcn = ilv ? ((n & 1) ? (N >> 1) + (n >> 1) : (n >> 1)) : n;
        t[i][tx] = w[(size_t)(k0 + i) * N + srcn];
    }
    __syncthreads();
    for (int i = ty; i < 32; i += 8) {
        float v = t[tx][i];
        __half h, l;
        split_h(v, h, l);
        hT[(size_t)(n0 + i) * K + k0 + tx] = h;
        lT[(size_t)(n0 + i) * K + k0 + tx] = l;
    }
}

// rmsnorm -> hi/lo half planes. One block (128 thr) per token.
__global__ void rmsnorm_k(const float* __restrict__ x, const float* __restrict__ w,
                          __half* __restrict__ yh, __half* __restrict__ yl) {
    __shared__ float red[128];
    size_t row = (size_t)blockIdx.x * DMODEL;
    int tid = threadIdx.x;
    float ss = 0.f;
    for (int i = tid; i < DMODEL; i += 128) {
        float v = x[row + i];
        ss += v * v;
    }
    float tot = bsum128(ss, red);
    float scale = rsqrtf(tot / (float)DMODEL + 1e-6f);
    for (int i = tid; i < DMODEL; i += 128) {
        __half h, l;
        split_h(x[row + i] * scale * w[i], h, l);
        yh[row + i] = h;
        yl[row + i] = l;
    }
}

// ---- 3xFP16 split GEMM, ldmatrix + cp.async ----
// mode 0: C = A@B ; mode 1: C += A@B ; mode 2: silu-gate epilogue:
//   cols interleaved (h1,h2); writes Dh/Dl[M][N/2] half planes, C unused.
__global__ __launch_bounds__(256) void sgemm_h3(const __half* __restrict__ Ah,
                                                const __half* __restrict__ Al,
                                                const __half* __restrict__ BTh,
                                                const __half* __restrict__ BTl,
                                                float* __restrict__ C,
                                                __half* __restrict__ Dh,
                                                __half* __restrict__ Dl,
                                                int M, int N, int K, int mode) {
    __shared__ __align__(16) __half As[2][2][128][24];   // [buf][plane][row][k]
    __shared__ __align__(16) __half Bs[2][2][128][24];
    int tid = threadIdx.x;
    int lane = tid & 31, warp = tid >> 5;
    int wm = warp >> 2, wn = warp & 3;
    int grp = lane >> 2, qid = lane & 3;
    int bm = blockIdx.y * 128, bn = blockIdx.x * 128;

    float acc[4][4][4];
#pragma unroll
    for (int i = 0; i < 4; i++)
#pragma unroll
        for (int j = 0; j < 4; j++)
#pragma unroll
            for (int t = 0; t < 4; t++) acc[i][j][t] = 0.f;

    int lrow = tid >> 1, lseg = (tid & 1) * 8;

#define LOADA(buf, k0)                                                              \
    {                                                                               \
        cpa16(sptr(&As[buf][0][lrow][lseg]), Ah + (size_t)(bm + lrow) * K + (k0) + lseg); \
        cpa16(sptr(&As[buf][1][lrow][lseg]), Al + (size_t)(bm + lrow) * K + (k0) + lseg); \
        cpa16(sptr(&Bs[buf][0][lrow][lseg]), BTh + (size_t)(bn + lrow) * K + (k0) + lseg); \
        cpa16(sptr(&Bs[buf][1][lrow][lseg]), BTl + (size_t)(bn + lrow) * K + (k0) + lseg); \
        cpa_commit();                                                               \
    }

    LOADA(0, 0);

    int arow = lane & 15, acg = (lane >> 4) * 8;   // ldmatrix row / k-group
    int nk = K >> 4;
    for (int kt = 0; kt < nk; kt++) {
        int buf = kt & 1;
        cpa_wait0();
        __syncthreads();
        if (kt + 1 < nk) LOADA(buf ^ 1, (kt + 1) << 4);

        uint32_t ah[4][4], al[4][4], bh[4][2], bl[4][2];
#pragma unroll
        for (int mt = 0; mt < 4; mt++) {
            int r = wm * 64 + mt * 16 + arow;
            ldsm4(ah[mt][0], ah[mt][1], ah[mt][2], ah[mt][3], sptr(&As[buf][0][r][acg]));
            ldsm4(al[mt][0], al[mt][1], al[mt][2], al[mt][3], sptr(&As[buf][1][r][acg]));
        }
#pragma unroll
        for (int ntp = 0; ntp < 2; ntp++) {
            int r = wn * 32 + ntp * 16 + arow;
            uint32_t m0, m1, m2, m3;
            ldsm4(m0, m1, m2, m3, sptr(&Bs[buf][0][r][acg]));
            bh[2 * ntp][0] = m0; bh[2 * ntp][1] = m2;
            bh[2 * ntp + 1][0] = m1; bh[2 * ntp + 1][1] = m3;
            ldsm4(m0, m1, m2, m3, sptr(&Bs[buf][1][r][acg]));
            bl[2 * ntp][0] = m0; bl[2 * ntp][1] = m2;
            bl[2 * ntp + 1][0] = m1; bl[2 * ntp + 1][1] = m3;
        }
#pragma unroll
        for (int mt = 0; mt < 4; mt++)
#pragma unroll
            for (int nt = 0; nt < 4; nt++) {
                mma16816(acc[mt][nt], al[mt], bh[nt]);
                mma16816(acc[mt][nt], ah[mt], bl[nt]);
                mma16816(acc[mt][nt], ah[mt], bh[nt]);
            }
        __syncthreads();
    }

    if (mode == 2) {
        int half_n = N >> 1;
#pragma unroll
        for (int mt = 0; mt < 4; mt++)
#pragma unroll
            for (int nt = 0; nt < 4; nt++) {
                int r0 = bm + wm * 64 + mt * 16 + grp;
                int j = (bn + wn * 32 + nt * 8 + 2 * qid) >> 1;
                float a0 = acc[mt][nt][0], b0 = acc[mt][nt][1];
                float a1 = acc[mt][nt][2], b1 = acc[mt][nt][3];
                float g0 = (a0 / (1.0f + __expf(-a0))) * b0;
                float g1 = (a1 / (1.0f + __expf(-a1))) * b1;
                __half h, l;
                split_h(g0, h, l);
                Dh[(size_t)r0 * half_n + j] = h;
                Dl[(size_t)r0 * half_n + j] = l;
                split_h(g1, h, l);
                Dh[(size_t)(r0 + 8) * half_n + j] = h;
                Dl[(size_t)(r0 + 8) * half_n + j] = l;
            }
    } else {
#pragma unroll
        for (int mt = 0; mt < 4; mt++)
#pragma unroll
            for (int nt = 0; nt < 4; nt++) {
                int r0 = bm + wm * 64 + mt * 16 + grp;
                int c0 = bn + wn * 32 + nt * 8 + 2 * qid;
                size_t i00 = (size_t)r0 * N + c0;
                size_t i10 = (size_t)(r0 + 8) * N + c0;
                if (mode == 1) {
                    C[i00]     += acc[mt][nt][0];
                    C[i00 + 1] += acc[mt][nt][1];
                    C[i10]     += acc[mt][nt][2];
                    C[i10 + 1] += acc[mt][nt][3];
                } else {
                    C[i00]     = acc[mt][nt][0];
                    C[i00 + 1] = acc[mt][nt][1];
                    C[i10]     = acc[mt][nt][2];
                    C[i10 + 1] = acc[mt][nt][3];
                }
            }
    }
#undef LOADA
}

// qkv row -> q/k (RoPE) and v, layout [bh][SEQ][64]. grid=ntok, block=256
__global__ void split_rope_k(const float* __restrict__ qkv,
                             float* __restrict__ Q, float* __restrict__ K,
                             float* __restrict__ V, int SEQ) {
    int tok = blockIdx.x;
    int b = tok / SEQ, s = tok % SEQ;
    const float* row = qkv + (size_t)tok * 1536;
    int tid = threadIdx.x;
    int h = tid >> 5, i = tid & 31;
    float q1 = row[h * 64 + i], q2 = row[h * 64 + i + 32];
    float k1 = row[512 + h * 64 + i], k2 = row[512 + h * 64 + i + 32];
    float inv = powf(1e-4f, (float)i * (1.0f / 32.0f));
    float ang = (float)s * inv;
    float c = cosf(ang), sn = sinf(ang);
    size_t base = ((size_t)(b * BH + h) * SEQ + s) * 64;
    Q[base + i]      =  q1 * c + q2 * sn;
    Q[base + i + 32] = -q1 * sn + q2 * c;
    K[base + i]      =  k1 * c + k2 * sn;
    K[base + i + 32] = -k1 * sn + k2 * c;
    for (int j = tid; j < 512; j += 256) {
        int hh = j >> 6, dd = j & 63;
        V[((size_t)(b * BH + hh) * SEQ + s) * 64 + dd] = row[1024 + j];
    }
}

// ---- tiled flash attention for encoder (block-causal at 64 + doc mask) ----
__global__ __launch_bounds__(128) void attn_tile_k(const float* __restrict__ Q,
                                                   const float* __restrict__ K,
                                                   const float* __restrict__ V,
                                                   __half* __restrict__ Oh,
                                                   __half* __restrict__ Ol,
                                                   const int* __restrict__ doc,
                                                   int SEQ) {
    extern __shared__ float sm[];
    float* Qs = sm;            // [64][68]
    float* Ks = sm + 4352;
    float* Vs = sm + 8704;
    float* Ps = sm + 13056;

    int qb = blockIdx.x, bh = blockIdx.y;
    int b = bh >> 3, h = bh & 7;
    int tid = threadIdx.x;
    int qg = tid >> 4, kg = tid & 15;
    int q0 = qg * 8, k0 = kg * 4, d0 = kg * 4;

    const float* Qb = Q + ((size_t)bh * SEQ + qb * 64) * 64;
    const float* Kb = K + (size_t)bh * SEQ * 64;
    const float* Vb = V + (size_t)bh * SEQ * 64;

    {
        const float4* src = (const float4*)Qb;
#pragma unroll
        for (int i = 0; i < 8; i++) {
            int fi = tid + 128 * i;
            int r = fi >> 4, c = fi & 15;
            *(float4*)(Qs + r * 68 + c * 4) = src[fi];
        }
    }
    int dqr[8];
#pragma unroll
    for (int j = 0; j < 8; j++) dqr[j] = doc[b * SEQ + qb * 64 + q0 + j];

    float4 o4[8];
    float mrow[8], lrow[8];
#pragma unroll
    for (int j = 0; j < 8; j++) {
        o4[j] = make_float4(0.f, 0.f, 0.f, 0.f);
        mrow[j] = -1e30f;
        lrow[j] = 0.f;
    }

    for (int kt = 0; kt <= qb; kt++) {
        int kbase = kt * 64;
        __syncthreads();
        {
            const float4* ksrc = (const float4*)(Kb + kbase * 64);
            const float4* vsrc = (const float4*)(Vb + kbase * 64);
#pragma unroll
            for (int i = 0; i < 8; i++) {
                int fi = tid + 128 * i;
                int r = fi >> 4, c = fi & 15;
                *(float4*)(Ks + r * 68 + c * 4) = ksrc[fi];
                *(float4*)(Vs + r * 68 + c * 4) = vsrc[fi];
            }
        }
        __syncthreads();

        float s[8][4];
#pragma unroll
        for (int j = 0; j < 8; j++)
#pragma unroll
            for (int i = 0; i < 4; i++) s[j][i] = 0.f;
#pragma unroll 4
        for (int dv = 0; dv < 16; dv++) {
            float4 kv[4];
#pragma unroll
            for (int i = 0; i < 4; i++) kv[i] = *(const float4*)(Ks + (k0 + i) * 68 + dv * 4);
#pragma unroll
            for (int j = 0; j < 8; j++) {
                float4 qv = *(const float4*)(Qs + (q0 + j) * 68 + dv * 4);
#pragma unroll
                for (int i = 0; i < 4; i++)
                    s[j][i] += qv.x * kv[i].x + qv.y * kv[i].y + qv.z * kv[i].z + qv.w * kv[i].w;
            }
        }
        int dkr[4];
#pragma unroll
        for (int i = 0; i < 4; i++) dkr[i] = doc[b * SEQ + kbase + k0 + i];
#pragma unroll
        for (int j = 0; j < 8; j++)
#pragma unroll
            for (int i = 0; i < 4; i++)
                s[j][i] = (dkr[i] == dqr[j]) ? s[j][i] * 0.125f : -6e30f;

#pragma unroll
        for (int j = 0; j < 8; j++) {
            float tm = fmaxf(fmaxf(s[j][0], s[j][1]), fmaxf(s[j][2], s[j][3]));
#pragma unroll
            for (int off = 1; off < 16; off <<= 1)
                tm = fmaxf(tm, __shfl_xor_sync(0xffffffffu, tm, off));
            float mnew = fmaxf(mrow[j], tm);
            float r = __expf(mrow[j] - mnew);
            float4 p;
            p.x = __expf(s[j][0] - mnew);
            p.y = __expf(s[j][1] - mnew);
            p.z = __expf(s[j][2] - mnew);
            p.w = __expf(s[j][3] - mnew);
            float ps = p.x + p.y + p.z + p.w;
#pragma unroll
            for (int off = 1; off < 16; off <<= 1)
                ps += __shfl_xor_sync(0xffffffffu, ps, off);
            lrow[j] = lrow[j] * r + ps;
            mrow[j] = mnew;
            o4[j].x *= r; o4[j].y *= r; o4[j].z *= r; o4[j].w *= r;
            *(float4*)(Ps + (q0 + j) * 68 + k0) = p;
        }
        __syncwarp();

#pragma unroll 4
        for (int kc = 0; kc < 16; kc++) {
            float4 vv[4];
#pragma unroll
            for (int i = 0; i < 4; i++) vv[i] = *(const float4*)(Vs + (kc * 4 + i) * 68 + d0);
#pragma unroll
            for (int j = 0; j < 8; j++) {
                float4 p = *(const float4*)(Ps + (q0 + j) * 68 + kc * 4);
                o4[j].x += p.x * vv[0].x + p.y * vv[1].x + p.z * vv[2].x + p.w * vv[3].x;
                o4[j].y += p.x * vv[0].y + p.y * vv[1].y + p.z * vv[2].y + p.w * vv[3].y;
                o4[j].z += p.x * vv[0].z + p.y * vv[1].z + p.z * vv[2].z + p.w * vv[3].z;
                o4[j].w += p.x * vv[0].w + p.y * vv[1].w + p.z * vv[2].w + p.w * vv[3].w;
            }
        }
    }

#pragma unroll
    for (int j = 0; j < 8; j++) {
        float inv = 1.0f / lrow[j];
        int row = qb * 64 + q0 + j;
        size_t base = (size_t)(b * SEQ + row) * DMODEL + h * 64 + d0;
        float vals[4] = {o4[j].x * inv, o4[j].y * inv, o4[j].z * inv, o4[j].w * inv};
#pragma unroll
        for (int i = 0; i < 4; i++) {
            __half hh, ll;
            split_h(vals[i], hh, ll);
            Oh[base + i] = hh;
            Ol[base + i] = ll;
        }
    }
}

// router attention (full attention within 72 tokens)
__global__ __launch_bounds__(128) void attn_k(const float* __restrict__ Q,
                                              const float* __restrict__ K,
                                              const float* __restrict__ V,
                                              __half* __restrict__ Oh,
                                              __half* __restrict__ Ol,
                                              int SEQ) {
    __shared__ float sq[64];
    __shared__ float sp[128];
    __shared__ float red[128];
    int q = blockIdx.x;
    int bh = blockIdx.y;
    int b = bh / BH, h = bh % BH;
    int tid = threadIdx.x;
    const float* Qr = Q + ((size_t)bh * SEQ + q) * 64;
    if (tid < 64) sq[tid] = Qr[tid];
    __syncthreads();

    int kend = SEQ;
    float m = -1e30f;
    for (int k = tid; k < kend; k += 128) {
        const float4* kr = (const float4*)(K + ((size_t)bh * SEQ + k) * 64);
        const float4* qr = (const float4*)sq;
        float a = 0.f;
#pragma unroll
        for (int i = 0; i < 16; i++) {
            float4 kv = kr[i], qv = qr[i];
            a += kv.x * qv.x + kv.y * qv.y + kv.z * qv.z + kv.w * qv.w;
        }
        sp[k] = a * 0.125f;
        m = fmaxf(m, a * 0.125f);
    }
    m = bmax128(m, red);

    float l = 0.f;
    for (int k = tid; k < kend; k += 128) {
        float e = __expf(sp[k] - m);
        sp[k] = e;
        l += e;
    }
    l = bsum128(l, red);

    int d = tid & 63, half = tid >> 6;
    float acc = 0.f;
    for (int k = half; k < kend; k += 2)
        acc += sp[k] * V[((size_t)bh * SEQ + k) * 64 + d];
    red[tid] = acc;
    __syncthreads();
    if (tid < 64) {
        float o = (red[tid] + red[tid + 64]) / l;
        size_t idx = (size_t)(b * SEQ + q) * DMODEL + h * 64 + tid;
        __half hh, ll;
        split_h(o, hh, ll);
        Oh[idx] = hh;
        Ol[idx] = ll;
    }
}

__global__ void build_xr_k(const float* __restrict__ x, const float* __restrict__ rt,
                           float* __restrict__ xr) {
    int i = blockIdx.x * blockDim.x + threadIdx.x;
    if (i >= NTOK_RTR * DMODEL) return;
    int blk = i / (SRTR * DMODEL);
    int rem = i % (SRTR * DMODEL);
    int t = rem / DMODEL, dd = rem % DMODEL;
    xr[i] = (t < 64) ? x[(size_t)(blk * 64 + t) * DMODEL + dd]
                     : rt[(size_t)(t - 64) * DMODEL + dd];
}

__global__ void gather_rows_k(const float* __restrict__ xr, __half* __restrict__ rh,
                              __half* __restrict__ rl) {
    int i = blockIdx.x * blockDim.x + threadIdx.x;
    if (i >= 512 * DMODEL) return;
    int row = i / DMODEL, dd = i % DMODEL;
    int blk = row >> 3, r = row & 7;
    __half h, l;
    split_h(xr[((size_t)blk * SRTR + 64 + r) * DMODEL + dd], h, l);
    rh[i] = h;
    rl[i] = l;
}

__global__ void knorm_k(const float* __restrict__ kr, const float* __restrict__ kg,
                        float* __restrict__ knr, float* __restrict__ kng) {
    int tid = threadIdx.x;
    int which = tid >> 9;
    int idx = tid & 511;
    int g = idx >> 4, e = idx & 15;
    const float* src = which ? kg : kr;
    const float* col = src + (size_t)g * 128 * 16 + e;
    float s = 0.f;
    for (int d = 0; d < 128; d++) { float v = col[d * 16]; s += v * v; }
    float n = fmaxf(sqrtf(s), 1e-12f);
    if (which) kng[idx] = n; else knr[idx] = n;
}

__global__ void logits_k(const float* __restrict__ outp,
                         const float* __restrict__ keys_r, const float* __restrict__ keys_g,
                         const float* __restrict__ knr, const float* __restrict__ kng,
                         float* __restrict__ rl, float* __restrict__ gl) {
    __shared__ float vr[128], vg[128], red[128];
    int g = blockIdx.x >> 6, bb = blockIdx.x & 63;
    int b = bb >> 5, l = bb & 31;
    int srcl = (l + 31) & 31;
    int r = g >> 2;
    const float* row = outp + (size_t)((b * 32 + srcl) * 8 + r) * 256;
    int tid = threadIdx.x;
    vr[tid] = row[tid];
    vg[tid] = row[128 + tid];
    float nr2 = bsum128(vr[tid] * vr[tid], red);
    float ng2 = bsum128(vg[tid] * vg[tid], red);
    float inr = 1.0f / fmaxf(sqrtf(nr2), 1e-12f);
    float ing = 1.0f / fmaxf(sqrtf(ng2), 1e-12f);
    if (tid < 16) {
        int e = tid;
        const float* kr = keys_r + (size_t)g * 128 * 16 + e;
        const float* kg = keys_g + (size_t)g * 128 * 16 + e;
        float dr = 0.f, dg = 0.f;
        for (int dd = 0; dd < 128; dd++) {
            dr += vr[dd] * kr[dd * 16];
            dg += vg[dd] * kg[dd * 16];
        }
        rl[(size_t)(g * 64 + bb) * 16 + e] = dr * inr / knr[g * 16 + e];
        gl[(size_t)(g * 64 + bb) * 16 + e] = dg * ing / kng[g * 16 + e];
    }
}

__global__ void topk_k(const float* __restrict__ rl, const float* __restrict__ gl,
                       float* __restrict__ out) {
    int t = blockIdx.x * blockDim.x + threadIdx.x;
    if (t >= 2048) return;
    const float* r = rl + (size_t)t * 16;
    const float* g = gl + (size_t)t * 16;
    int i1 = 0; float v1 = r[0];
    for (int e = 1; e < 16; e++) if (r[e] > v1) { v1 = r[e]; i1 = e; }
    int i2 = -1; float v2 = -1e30f;
    for (int e = 0; e < 16; e++) {
        if (e == i1) continue;
        if (r[e] > v2) { v2 = r[e]; i2 = e; }
    }
    out[(size_t)t * 2 + 0] = v1;
    out[(size_t)t * 2 + 1] = v2;
    out[4096 + (size_t)t * 2 + 0] = g[i1];
    out[4096 + (size_t)t * 2 + 1] = g[i2];
}

// ---------------- host orchestration ----------------
#define ATTN_SMEM 69632

static void run_layer(float* cur, size_t qkvo, size_t oo, size_t upo, size_t dno,
                      const float* n1, const float* n2,
                      int ntok, int SEQ, int enc, const int* doc,
                      float* sb, __half* hb_) {
    float*  qkv = sb + OFF_QKV;
    float*  qb  = sb + OFF_Q;
    float*  kb  = sb + OFF_K;
    float*  vb  = sb + OFF_V;
    float*  hbuf = sb + OFF_H;
    __half* xnh = hb_ + HO_XNH; __half* xnl = hb_ + HO_XNL;
    __half* ath = hb_ + HO_ATTH; __half* atl = hb_ + HO_ATTL;
    __half* ach = hb_ + HO_ACTH; __half* acl = hb_ + HO_ACTL;
    __half* wh = hb_ + HO_WH;  __half* wl = hb_ + HO_WL;

    rmsnorm_k<<<ntok, 128>>>(cur, n1, xnh, xnl);
    sgemm_h3<<<dim3(1536 / 128, ntok / 128), 256>>>(xnh, xnl, wh + qkvo, wl + qkvo, qkv,
                                                    nullptr, nullptr, ntok, 1536, 512, 0);
    split_rope_k<<<ntok, 256>>>(qkv, qb, kb, vb, SEQ);
    if (enc)
        attn_tile_k<<<dim3(SEQ / 64, (ntok / SEQ) * BH), 128, ATTN_SMEM>>>(qb, kb, vb, ath, atl, doc, SEQ);
    else
        attn_k<<<dim3(SEQ, (ntok / SEQ) * BH), 128>>>(qb, kb, vb, ath, atl, SEQ);
    sgemm_h3<<<dim3(512 / 128, ntok / 128), 256>>>(ath, atl, wh + oo, wl + oo, cur,
                                                   nullptr, nullptr, ntok, 512, 512, 1);
    rmsnorm_k<<<ntok, 128>>>(cur, n2, xnh, xnl);
    // up-GEMM with fused SiLU-gate epilogue (interleaved weights)
    sgemm_h3<<<dim3(2048 / 128, ntok / 128), 256>>>(xnh, xnl, wh + upo, wl + upo, hbuf,
                                                    ach, acl, ntok, 2048, 512, 2);
    sgemm_h3<<<dim3(512 / 128, ntok / 128), 256>>>(ach, acl, wh + dno, wl + dno, cur,
                                                   nullptr, nullptr, ntok, 512, 1024, 1);
}

extern "C" void kernel_launch(void* const* d_in, const int* in_sizes, int n_in,
                              void* d_out, int out_size) {
    const float* x_in   = (const float*)d_in[0];
    const int*   doc    = (const int*)d_in[1];
    const float* rt     = (const float*)d_in[2];
    const float* out_w  = (const float*)d_in[3];
    const float* keys_r = (const float*)d_in[4];
    const float* keys_g = (const float*)d_in[5];
    const float* e_qkv  = (const float*)d_in[6];
    const float* e_o    = (const float*)d_in[7];
    const float* e_up   = (const float*)d_in[8];
    const float* e_dn   = (const float*)d_in[9];
    const float* e_n1   = (const float*)d_in[10];
    const float* e_n2   = (const float*)d_in[11];
    const float* r_qkv  = (const float*)d_in[12];
    const float* r_o    = (const float*)d_in[13];
    const float* r_up   = (const float*)d_in[14];
    const float* r_dn   = (const float*)d_in[15];
    const float* r_n1   = (const float*)d_in[16];
    const float* r_n2   = (const float*)d_in[17];
    float* out = (float*)d_out;

    static int smem_set = 0;
    if (!smem_set) {
        cudaFuncSetAttribute(attn_tile_k, cudaFuncAttributeMaxDynamicSharedMemorySize, ATTN_SMEM);
        smem_set = 1;
    }

    float* sb;
    cudaGetSymbolAddress((void**)&sb, g_s);
    __half* hb_;
    cudaGetSymbolAddress((void**)&hb_, g_h);

    float* xbuf = sb + OFF_X;
    float* xr   = sb + OFF_XR;
    float* outp = sb + OFF_OUT;
    float* knr  = sb + OFF_KNR;
    float* kng  = sb + OFF_KNG;
    float* rl   = sb + OFF_RL;
    float* gl   = sb + OFF_GL;
    __half* wh = hb_ + HO_WH;
    __half* wl = hb_ + HO_WL;
    __half* rowsh = hb_ + HO_ROWSH;
    __half* rowsl = hb_ + HO_ROWSL;

    // pre-split all weights, transposed to [N][K]; up weights interleaved
    for (int i = 0; i < 4; i++) {
        wsplitT_k<<<dim3(1536 / 32, 512 / 32), dim3(32, 8)>>>(
            e_qkv + (size_t)i * 512 * 1536, wh + WO_EQ + (size_t)i * 786432,
            wl + WO_EQ + (size_t)i * 786432, 512, 1536, 0);
        wsplitT_k<<<dim3(512 / 32, 512 / 32), dim3(32, 8)>>>(
            e_o + (size_t)i * 512 * 512, wh + WO_EO + (size_t)i * 262144,
            wl + WO_EO + (size_t)i * 262144, 512, 512, 0);
        wsplitT_k<<<dim3(2048 / 32, 512 / 32), dim3(32, 8)>>>(
            e_up + (size_t)i * 512 * 2048, wh + WO_EU + (size_t)i * 1048576,
            wl + WO_EU + (size_t)i * 1048576, 512, 2048, 1);
        wsplitT_k<<<dim3(512 / 32, 1024 / 32), dim3(32, 8)>>>(
            e_dn + (size_t)i * 1024 * 512, wh + WO_ED + (size_t)i * 524288,
            wl + WO_ED + (size_t)i * 524288, 1024, 512, 0);
    }
    for (int i = 0; i < 2; i++) {
        wsplitT_k<<<dim3(1536 / 32, 512 / 32), dim3(32, 8)>>>(
            r_qkv + (size_t)i * 512 * 1536, wh + WO_RQ + (size_t)i * 786432,
            wl + WO_RQ + (size_t)i * 786432, 512, 1536, 0);
        wsplitT_k<<<dim3(512 / 32, 512 / 32), dim3(32, 8)>>>(
            r_o + (size_t)i * 512 * 512, wh + WO_RO + (size_t)i * 262144,
            wl + WO_RO + (size_t)i * 262144, 512, 512, 0);
        wsplitT_k<<<dim3(2048 / 32, 512 / 32), dim3(32, 8)>>>(
            r_up + (size_t)i * 512 * 2048, wh + WO_RU + (size_t)i * 1048576,
            wl + WO_RU + (size_t)i * 1048576, 512, 2048, 1);
        wsplitT_k<<<dim3(512 / 32, 1024 / 32), dim3(32, 8)>>>(
            r_dn + (size_t)i * 1024 * 512, wh + WO_RD + (size_t)i * 524288,
            wl + WO_RD + (size_t)i * 524288, 1024, 512, 0);
    }
    wsplitT_k<<<dim3(256 / 32, 512 / 32), dim3(32, 8)>>>(out_w, wh + WO_OUT, wl + WO_OUT, 512, 256, 0);

    copy_k<<<(NTOK_ENC * DMODEL + 255) / 256, 256>>>(x_in, xbuf, NTOK_ENC * DMODEL);

    for (int i = 0; i < 4; i++) {
        run_layer(xbuf,
                  WO_EQ + (size_t)i * 786432,
                  WO_EO + (size_t)i * 262144,
                  WO_EU + (size_t)i * 1048576,
                  WO_ED + (size_t)i * 524288,
                  e_n1 + (size_t)i * 512, e_n2 + (size_t)i * 512,
                  NTOK_ENC, SENC, 1, doc, sb, hb_);
    }

    build_xr_k<<<(NTOK_RTR * DMODEL + 255) / 256, 256>>>(xbuf, rt, xr);

    for (int i = 0; i < 2; i++) {
        run_layer(xr,
                  WO_RQ + (size_t)i * 786432,
                  WO_RO + (size_t)i * 262144,
                  WO_RU + (size_t)i * 1048576,
                  WO_RD + (size_t)i * 524288,
                  r_n1 + (size_t)i * 512, r_n2 + (size_t)i * 512,
                  NTOK_RTR, SRTR, 0, nullptr, sb, hb_);
    }

    gather_rows_k<<<(512 * DMODEL + 255) / 256, 256>>>(xr, rowsh, rowsl);
    sgemm_h3<<<dim3(256 / 128, 512 / 128), 256>>>(rowsh, rowsl, wh + WO_OUT, wl + WO_OUT, outp,
                                                  nullptr, nullptr, 512, 256, 512, 0);

    knorm_k<<<1, 1024>>>(keys_r, keys_g, knr, kng);
    logits_k<<<32 * 64, 128>>>(outp, keys_r, keys_g, knr, kng, rl, gl);
    topk_k<<<16, 128>>>(rl, gl, out);
}

// round 9
// speedup vs baseline: 2.4832x; 1.0089x over previous
#include <cuda_runtime.h>
#include <cuda_fp16.h>
#include <math.h>
#include <stdint.h>

// Model constants
#define BH      8
#define HDIM    64
#define DMODEL  512
#define SENC    2048
#define SRTR    72
#define NTOK_ENC 4096
#define NTOK_RTR 4608
#define FFH     1024

// ---- fp32 scratch (float offsets) ----
#define OFF_QKV   0ull                 // 4608*1536
#define OFF_H     14155776ull
#define OFF_X     23592960ull
#define OFF_XR    25952256ull
#define OFF_OUT   28311552ull          // 512*256
#define OFF_KNR   28442624ull
#define OFF_KNG   28443136ull
#define OFF_RL    28443648ull
#define OFF_GL    28476416ull
#define SCRATCH_FLOATS 28509184ull
__device__ float g_s[SCRATCH_FLOATS];

// ---- fp16 scratch (half offsets) ----
#define HO_XNH   0ull                  // 4608*512
#define HO_XNL   2359296ull
#define HO_ATTH  4718592ull
#define HO_ATTL  7077888ull
#define HO_ACTH  9437184ull            // 4608*1024
#define HO_ACTL  14155776ull
#define HO_ROWSH 18874368ull           // 512*512
#define HO_ROWSL 19136512ull
#define HO_WH    19398656ull           // all weights (transposed), 15859712 halves
#define HO_WL    35258368ull
#define HO_QH    51118080ull           // 8 planes x 4608*512
#define HO_QL    53477376ull
#define HO_KH    55836672ull
#define HO_KL    58195968ull
#define HO_VH    60555264ull
#define HO_VL    62914560ull
#define HO_VTH   65273856ull
#define HO_VTL   67633152ull
#define SCRATCH_HALVES 69992448ull
__device__ __half g_h[SCRATCH_HALVES];

// weight-plane sub-offsets (halves)
#define WO_EQ   0ull         // 4 x [1536][512]
#define WO_EO   3145728ull   // 4 x [512][512]
#define WO_EU   4194304ull   // 4 x [2048][512] (interleaved h1/h2)
#define WO_ED   8388608ull   // 4 x [512][1024]
#define WO_RQ   10485760ull
#define WO_RO   12058624ull
#define WO_RU   12582912ull
#define WO_RD   14680064ull
#define WO_OUT  15728640ull  // [256][512]

// ---------------- helpers ----------------
__device__ __forceinline__ float bsum128(float v, volatile float* red) {
    int tid = threadIdx.x;
    red[tid] = v;
    for (int off = 64; off >= 1; off >>= 1) {
        __syncthreads();
        if (tid < off) red[tid] += red[tid + off];
    }
    __syncthreads();
    float r = red[0];
    __syncthreads();
    return r;
}

__device__ __forceinline__ float bmax128(float v, volatile float* red) {
    int tid = threadIdx.x;
    red[tid] = v;
    for (int off = 64; off >= 1; off >>= 1) {
        __syncthreads();
        if (tid < off) red[tid] = fmaxf(red[tid], red[tid + off]);
    }
    __syncthreads();
    float r = red[0];
    __syncthreads();
    return r;
}

__device__ __forceinline__ void split_h(float v, __half& hi, __half& lo) {
    hi = __float2half_rn(v);
    lo = __float2half_rn(v - __half2float(hi));
}

__device__ __forceinline__ void mma16816(float* c, const uint32_t* a, const uint32_t* b) {
    asm volatile(
        "mma.sync.aligned.m16n8k16.row.col.f32.f16.f16.f32 "
        "{%0,%1,%2,%3}, {%4,%5,%6,%7}, {%8,%9}, {%0,%1,%2,%3};"
        : "+f"(c[0]), "+f"(c[1]), "+f"(c[2]), "+f"(c[3])
        : "r"(a[0]), "r"(a[1]), "r"(a[2]), "r"(a[3]), "r"(b[0]), "r"(b[1]));
}

__device__ __forceinline__ uint32_t sptr(const void* p) {
    return (uint32_t)__cvta_generic_to_shared(p);
}

__device__ __forceinline__ void ldsm4(uint32_t& r0, uint32_t& r1, uint32_t& r2,
                                      uint32_t& r3, uint32_t addr) {
    asm volatile("ldmatrix.sync.aligned.m8n8.x4.shared.b16 {%0,%1,%2,%3}, [%4];"
                 : "=r"(r0), "=r"(r1), "=r"(r2), "=r"(r3) : "r"(addr));
}

__device__ __forceinline__ void cpa16(uint32_t dst, const void* src) {
    asm volatile("cp.async.cg.shared.global [%0], [%1], 16;" :: "r"(dst), "l"(src));
}
__device__ __forceinline__ void cpa_commit() { asm volatile("cp.async.commit_group;"); }
__device__ __forceinline__ void cpa_wait0() { asm volatile("cp.async.wait_group 0;"); }

__device__ __forceinline__ uint32_t h2u(__half2 h) { return *(uint32_t*)&h; }

// ---------------- kernels ----------------
__global__ void copy_k(const float* __restrict__ src, float* __restrict__ dst, int n) {
    int i = blockIdx.x * blockDim.x + threadIdx.x;
    if (i < n) dst[i] = src[i];
}

// transpose + split weights
__global__ void wsplitT_k(const float* __restrict__ w, __half* __restrict__ hT,
                          __half* __restrict__ lT, int K, int N, int ilv) {
    __shared__ float t[32][33];
    int n0 = blockIdx.x * 32, k0 = blockIdx.y * 32;
    int tx = threadIdx.x, ty = threadIdx.y;
    for (int i = ty; i < 32; i += 8) {
        int n = n0 + tx;
        int srcn = ilv ? ((n & 1) ? (N >> 1) + (n >> 1) : (n >> 1)) : n;
        t[i][tx] = w[(size_t)(k0 + i) * N + srcn];
    }
    __syncthreads();
    for (int i = ty; i < 32; i += 8) {
        float v = t[tx][i];
        __half h, l;
        split_h(v, h, l);
        hT[(size_t)(n0 + i) * K + k0 + tx] = h;
        lT[(size_t)(n0 + i) * K + k0 + tx] = l;
    }
}

__global__ void rmsnorm_k(const float* __restrict__ x, const float* __restrict__ w,
                          __half* __restrict__ yh, __half* __restrict__ yl) {
    __shared__ float red[128];
    size_t row = (size_t)blockIdx.x * DMODEL;
    int tid = threadIdx.x;
    float ss = 0.f;
    for (int i = tid; i < DMODEL; i += 128) {
        float v = x[row + i];
        ss += v * v;
    }
    float tot = bsum128(ss, red);
    float scale = rsqrtf(tot / (float)DMODEL + 1e-6f);
    for (int i = tid; i < DMODEL; i += 128) {
        __half h, l;
        split_h(x[row + i] * scale * w[i], h, l);
        yh[row + i] = h;
        yl[row + i] = l;
    }
}

// ---- 3xFP16 split GEMM, ldmatrix + cp.async ----
__global__ __launch_bounds__(256) void sgemm_h3(const __half* __restrict__ Ah,
                                                const __half* __restrict__ Al,
                                                const __half* __restrict__ BTh,
                                                const __half* __restrict__ BTl,
                                                float* __restrict__ C,
                                                __half* __restrict__ Dh,
                                                __half* __restrict__ Dl,
                                                int M, int N, int K, int mode) {
    __shared__ __align__(16) __half As[2][2][128][24];
    __shared__ __align__(16) __half Bs[2][2][128][24];
    int tid = threadIdx.x;
    int lane = tid & 31, warp = tid >> 5;
    int wm = warp >> 2, wn = warp & 3;
    int grp = lane >> 2, qid = lane & 3;
    int bm = blockIdx.y * 128, bn = blockIdx.x * 128;

    float acc[4][4][4];
#pragma unroll
    for (int i = 0; i < 4; i++)
#pragma unroll
        for (int j = 0; j < 4; j++)
#pragma unroll
            for (int t = 0; t < 4; t++) acc[i][j][t] = 0.f;

    int lrow = tid >> 1, lseg = (tid & 1) * 8;

#define LOADA(buf, k0)                                                              \
    {                                                                               \
        cpa16(sptr(&As[buf][0][lrow][lseg]), Ah + (size_t)(bm + lrow) * K + (k0) + lseg); \
        cpa16(sptr(&As[buf][1][lrow][lseg]), Al + (size_t)(bm + lrow) * K + (k0) + lseg); \
        cpa16(sptr(&Bs[buf][0][lrow][lseg]), BTh + (size_t)(bn + lrow) * K + (k0) + lseg); \
        cpa16(sptr(&Bs[buf][1][lrow][lseg]), BTl + (size_t)(bn + lrow) * K + (k0) + lseg); \
        cpa_commit();                                                               \
    }

    LOADA(0, 0);

    int arow = lane & 15, acg = (lane >> 4) * 8;
    int nk = K >> 4;
    for (int kt = 0; kt < nk; kt++) {
        int buf = kt & 1;
        cpa_wait0();
        __syncthreads();
        if (kt + 1 < nk) LOADA(buf ^ 1, (kt + 1) << 4);

        uint32_t ah[4][4], al[4][4], bh[4][2], bl[4][2];
#pragma unroll
        for (int mt = 0; mt < 4; mt++) {
            int r = wm * 64 + mt * 16 + arow;
            ldsm4(ah[mt][0], ah[mt][1], ah[mt][2], ah[mt][3], sptr(&As[buf][0][r][acg]));
            ldsm4(al[mt][0], al[mt][1], al[mt][2], al[mt][3], sptr(&As[buf][1][r][acg]));
        }
#pragma unroll
        for (int ntp = 0; ntp < 2; ntp++) {
            int r = wn * 32 + ntp * 16 + arow;
            uint32_t m0, m1, m2, m3;
            ldsm4(m0, m1, m2, m3, sptr(&Bs[buf][0][r][acg]));
            bh[2 * ntp][0] = m0; bh[2 * ntp][1] = m2;
            bh[2 * ntp + 1][0] = m1; bh[2 * ntp + 1][1] = m3;
            ldsm4(m0, m1, m2, m3, sptr(&Bs[buf][1][r][acg]));
            bl[2 * ntp][0] = m0; bl[2 * ntp][1] = m2;
            bl[2 * ntp + 1][0] = m1; bl[2 * ntp + 1][1] = m3;
        }
#pragma unroll
        for (int mt = 0; mt < 4; mt++)
#pragma unroll
            for (int nt = 0; nt < 4; nt++) {
                mma16816(acc[mt][nt], al[mt], bh[nt]);
                mma16816(acc[mt][nt], ah[mt], bl[nt]);
                mma16816(acc[mt][nt], ah[mt], bh[nt]);
            }
        __syncthreads();
    }

    if (mode == 2) {
        int half_n = N >> 1;
#pragma unroll
        for (int mt = 0; mt < 4; mt++)
#pragma unroll
            for (int nt = 0; nt < 4; nt++) {
                int r0 = bm + wm * 64 + mt * 16 + grp;
                int j = (bn + wn * 32 + nt * 8 + 2 * qid) >> 1;
                float a0 = acc[mt][nt][0], b0 = acc[mt][nt][1];
                float a1 = acc[mt][nt][2], b1 = acc[mt][nt][3];
                float g0 = (a0 / (1.0f + __expf(-a0))) * b0;
                float g1 = (a1 / (1.0f + __expf(-a1))) * b1;
                __half h, l;
                split_h(g0, h, l);
                Dh[(size_t)r0 * half_n + j] = h;
                Dl[(size_t)r0 * half_n + j] = l;
                split_h(g1, h, l);
                Dh[(size_t)(r0 + 8) * half_n + j] = h;
                Dl[(size_t)(r0 + 8) * half_n + j] = l;
            }
    } else {
#pragma unroll
        for (int mt = 0; mt < 4; mt++)
#pragma unroll
            for (int nt = 0; nt < 4; nt++) {
                int r0 = bm + wm * 64 + mt * 16 + grp;
                int c0 = bn + wn * 32 + nt * 8 + 2 * qid;
                size_t i00 = (size_t)r0 * N + c0;
                size_t i10 = (size_t)(r0 + 8) * N + c0;
                if (mode == 1) {
                    C[i00]     += acc[mt][nt][0];
                    C[i00 + 1] += acc[mt][nt][1];
                    C[i10]     += acc[mt][nt][2];
                    C[i10 + 1] += acc[mt][nt][3];
                } else {
                    C[i00]     = acc[mt][nt][0];
                    C[i00 + 1] = acc[mt][nt][1];
                    C[i10]     = acc[mt][nt][2];
                    C[i10 + 1] = acc[mt][nt][3];
                }
            }
    }
#undef LOADA
}

// qkv row -> q/k (RoPE) and v, written as hi/lo half planes [bh][SEQ][64]
__global__ void split_rope_k(const float* __restrict__ qkv,
                             __half* __restrict__ Qh, __half* __restrict__ Ql,
                             __half* __restrict__ Kh, __half* __restrict__ Kl,
                             __half* __restrict__ Vh, __half* __restrict__ Vl,
                             int SEQ) {
    int tok = blockIdx.x;
    int b = tok / SEQ, s = tok % SEQ;
    const float* row = qkv + (size_t)tok * 1536;
    int tid = threadIdx.x;
    int h = tid >> 5, i = tid & 31;
    float q1 = row[h * 64 + i], q2 = row[h * 64 + i + 32];
    float k1 = row[512 + h * 64 + i], k2 = row[512 + h * 64 + i + 32];
    float inv = powf(1e-4f, (float)i * (1.0f / 32.0f));
    float ang = (float)s * inv;
    float c = cosf(ang), sn = sinf(ang);
    size_t base = ((size_t)(b * BH + h) * SEQ + s) * 64;
    __half hh, ll;
    split_h(q1 * c + q2 * sn, hh, ll);      Qh[base + i] = hh;      Ql[base + i] = ll;
    split_h(-q1 * sn + q2 * c, hh, ll);     Qh[base + i + 32] = hh; Ql[base + i + 32] = ll;
    split_h(k1 * c + k2 * sn, hh, ll);      Kh[base + i] = hh;      Kl[base + i] = ll;
    split_h(-k1 * sn + k2 * c, hh, ll);     Kh[base + i + 32] = hh; Kl[base + i + 32] = ll;
    for (int j = tid; j < 512; j += 256) {
        int hd = j >> 6, dd = j & 63;
        split_h(row[1024 + j], hh, ll);
        size_t vi = ((size_t)(b * BH + hd) * SEQ + s) * 64 + dd;
        Vh[vi] = hh;
        Vl[vi] = ll;
    }
}

// V [bh][s][64] -> Vt [bh][64][s], both planes. grid (SEQ/64, bh_total), 256 thr.
__global__ void vtrans_k(const __half* __restrict__ Vh, const __half* __restrict__ Vl,
                         __half* __restrict__ Vth, __half* __restrict__ Vtl, int SEQ) {
    __shared__ __half t[2][64][72];
    int sc = blockIdx.x * 64;
    int bh = blockIdx.y;
    int tid = threadIdx.x;
    for (int i = tid; i < 512; i += 256) {
        int r = i >> 3, c = (i & 7) * 8;
        *(uint4*)&t[0][r][c] = *(const uint4*)(Vh + ((size_t)bh * SEQ + sc + r) * 64 + c);
        *(uint4*)&t[1][r][c] = *(const uint4*)(Vl + ((size_t)bh * SEQ + sc + r) * 64 + c);
    }
    __syncthreads();
    for (int i = tid; i < 4096; i += 256) {
        int d = i >> 6, s = i & 63;
        Vth[((size_t)bh * 64 + d) * SEQ + sc + s] = t[0][s][d];
        Vtl[((size_t)bh * 64 + d) * SEQ + sc + s] = t[1][s][d];
    }
}

// ---- tensor-core flash attention, 3xFP16 split (encoder path) ----
// grid (SEQ/64, NB*BH), 128 thr (4 warps; warp -> 16 q rows).
#define ATS 72
#define AMMA_SMEM (6 * 64 * ATS * 2 + 256)
__global__ __launch_bounds__(128) void attn_mma_k(
        const __half* __restrict__ Qh, const __half* __restrict__ Ql,
        const __half* __restrict__ Kh, const __half* __restrict__ Kl,
        const __half* __restrict__ Vth, const __half* __restrict__ Vtl,
        __half* __restrict__ Oh, __half* __restrict__ Ol,
        const int* __restrict__ doc, int SEQ) {
    extern __shared__ __half hsm[];
    __half* Qsh = hsm;
    __half* Qsl = hsm + 64 * ATS;
    __half* Ksh = hsm + 2 * 64 * ATS;
    __half* Ksl = hsm + 3 * 64 * ATS;
    __half* Vsh = hsm + 4 * 64 * ATS;   // [d][key]
    __half* Vsl = hsm + 5 * 64 * ATS;
    int* sdoc = (int*)(hsm + 6 * 64 * ATS);

    int qb = blockIdx.x, bh = blockIdx.y;
    int b = bh >> 3, h = bh & 7;
    int tid = threadIdx.x, lane = tid & 31, warp = tid >> 5;
    int grp = lane >> 2, qid = lane & 3;
    int arow = lane & 15, acg = (lane >> 4) * 8;

    const __half* Qbh = Qh + ((size_t)bh * SEQ + qb * 64) * 64;
    const __half* Qbl = Ql + ((size_t)bh * SEQ + qb * 64) * 64;
    for (int i = tid; i < 512; i += 128) {
        int r = i >> 3, c = (i & 7) * 8;
        *(uint4*)(Qsh + r * ATS + c) = *(const uint4*)(Qbh + r * 64 + c);
        *(uint4*)(Qsl + r * ATS + c) = *(const uint4*)(Qbl + r * 64 + c);
    }
    __syncthreads();

    uint32_t qfh[4][4], qfl[4][4];
#pragma unroll
    for (int ds = 0; ds < 4; ds++) {
        ldsm4(qfh[ds][0], qfh[ds][1], qfh[ds][2], qfh[ds][3],
              sptr(Qsh + (warp * 16 + arow) * ATS + ds * 16 + acg));
        ldsm4(qfl[ds][0], qfl[ds][1], qfl[ds][2], qfl[ds][3],
              sptr(Qsl + (warp * 16 + arow) * ATS + ds * 16 + acg));
    }
    int dq0 = doc[b * SEQ + qb * 64 + warp * 16 + grp];
    int dq1 = doc[b * SEQ + qb * 64 + warp * 16 + grp + 8];

    float o[8][4];
#pragma unroll
    for (int j = 0; j < 8; j++)
#pragma unroll
        for (int t = 0; t < 4; t++) o[j][t] = 0.f;
    float m0r = -1e30f, m1r = -1e30f, l0 = 0.f, l1 = 0.f;

    const __half* Kbh = Kh + (size_t)bh * SEQ * 64;
    const __half* Kbl = Kl + (size_t)bh * SEQ * 64;
    const __half* Vbh = Vth + (size_t)bh * 64 * SEQ;
    const __half* Vbl = Vtl + (size_t)bh * 64 * SEQ;

    for (int kt = 0; kt <= qb; kt++) {
        int kbase = kt * 64;
        __syncthreads();
        for (int i = tid; i < 512; i += 128) {
            int r = i >> 3, c = (i & 7) * 8;
            *(uint4*)(Ksh + r * ATS + c) = *(const uint4*)(Kbh + (size_t)(kbase + r) * 64 + c);
            *(uint4*)(Ksl + r * ATS + c) = *(const uint4*)(Kbl + (size_t)(kbase + r) * 64 + c);
            *(uint4*)(Vsh + r * ATS + c) = *(const uint4*)(Vbh + (size_t)r * SEQ + kbase + c);
            *(uint4*)(Vsl + r * ATS + c) = *(const uint4*)(Vbl + (size_t)r * SEQ + kbase + c);
        }
        if (tid < 64) sdoc[tid] = doc[b * SEQ + kbase + tid];
        __syncthreads();

        // ---- QK^T ----
        float sc[8][4];
#pragma unroll
        for (int j = 0; j < 8; j++)
#pragma unroll
            for (int t = 0; t < 4; t++) sc[j][t] = 0.f;
#pragma unroll
        for (int ds = 0; ds < 4; ds++) {
            uint32_t kfh[8][2], kfl[8][2];
#pragma unroll
            for (int np = 0; np < 4; np++) {
                uint32_t m0, m1, m2, m3;
                ldsm4(m0, m1, m2, m3, sptr(Ksh + (np * 16 + arow) * ATS + ds * 16 + acg));
                kfh[2 * np][0] = m0; kfh[2 * np][1] = m2;
                kfh[2 * np + 1][0] = m1; kfh[2 * np + 1][1] = m3;
                ldsm4(m0, m1, m2, m3, sptr(Ksl + (np * 16 + arow) * ATS + ds * 16 + acg));
                kfl[2 * np][0] = m0; kfl[2 * np][1] = m2;
                kfl[2 * np + 1][0] = m1; kfl[2 * np + 1][1] = m3;
            }
#pragma unroll
            for (int j = 0; j < 8; j++) {
                mma16816(sc[j], qfl[ds], kfh[j]);
                mma16816(sc[j], qfh[ds], kfl[j]);
                mma16816(sc[j], qfh[ds], kfh[j]);
            }
        }

        // ---- mask + scale ----
#pragma unroll
        for (int j = 0; j < 8; j++) {
            int dk0 = sdoc[8 * j + 2 * qid], dk1 = sdoc[8 * j + 2 * qid + 1];
            sc[j][0] = (dk0 == dq0) ? sc[j][0] * 0.125f : -6e30f;
            sc[j][1] = (dk1 == dq0) ? sc[j][1] * 0.125f : -6e30f;
            sc[j][2] = (dk0 == dq1) ? sc[j][2] * 0.125f : -6e30f;
            sc[j][3] = (dk1 == dq1) ? sc[j][3] * 0.125f : -6e30f;
        }

        // ---- online softmax (rows grp / grp+8; reduce over 4-lane qid group) ----
        float tm0 = -1e30f, tm1 = -1e30f;
#pragma unroll
        for (int j = 0; j < 8; j++) {
            tm0 = fmaxf(tm0, fmaxf(sc[j][0], sc[j][1]));
            tm1 = fmaxf(tm1, fmaxf(sc[j][2], sc[j][3]));
        }
#pragma unroll
        for (int off = 1; off < 4; off <<= 1) {
            tm0 = fmaxf(tm0, __shfl_xor_sync(0xffffffffu, tm0, off));
            tm1 = fmaxf(tm1, __shfl_xor_sync(0xffffffffu, tm1, off));
        }
        float mn0 = fmaxf(m0r, tm0), mn1 = fmaxf(m1r, tm1);
        float r0 = __expf(m0r - mn0), r1 = __expf(m1r - mn1);

        uint32_t pfh[8][2], pfl[8][2];
        float ps0 = 0.f, ps1 = 0.f;
#pragma unroll
        for (int j = 0; j < 8; j++) {
            float p0 = __expf(sc[j][0] - mn0), p1 = __expf(sc[j][1] - mn0);
            float p2 = __expf(sc[j][2] - mn1), p3 = __expf(sc[j][3] - mn1);
            ps0 += p0 + p1; ps1 += p2 + p3;
            __half2 hA = __floats2half2_rn(p0, p1);
            __half2 hB = __floats2half2_rn(p2, p3);
            pfh[j][0] = h2u(hA);
            pfh[j][1] = h2u(hB);
            __half2 lA = __floats2half2_rn(p0 - __half2float(__low2half(hA)),
                                           p1 - __half2float(__high2half(hA)));
            __half2 lB = __floats2half2_rn(p2 - __half2float(__low2half(hB)),
                                           p3 - __half2float(__high2half(hB)));
            pfl[j][0] = h2u(lA);
            pfl[j][1] = h2u(lB);
        }
#pragma unroll
        for (int off = 1; off < 4; off <<= 1) {
            ps0 += __shfl_xor_sync(0xffffffffu, ps0, off);
            ps1 += __shfl_xor_sync(0xffffffffu, ps1, off);
        }
        l0 = l0 * r0 + ps0;
        l1 = l1 * r1 + ps1;
        m0r = mn0; m1r = mn1;
#pragma unroll
        for (int j = 0; j < 8; j++) {
            o[j][0] *= r0; o[j][1] *= r0; o[j][2] *= r1; o[j][3] *= r1;
        }

        // ---- P @ V (V^T tiles, same [n][k] ldsm pattern) ----
#pragma unroll
        for (int ks = 0; ks < 4; ks++) {
            uint32_t pah[4] = {pfh[2 * ks][0], pfh[2 * ks][1], pfh[2 * ks + 1][0], pfh[2 * ks + 1][1]};
            uint32_t pal[4] = {pfl[2 * ks][0], pfl[2 * ks][1], pfl[2 * ks + 1][0], pfl[2 * ks + 1][1]};
            uint32_t vfh[8][2], vfl[8][2];
#pragma unroll
            for (int np = 0; np < 4; np++) {
                uint32_t m0, m1, m2, m3;
                ldsm4(m0, m1, m2, m3, sptr(Vsh + (np * 16 + arow) * ATS + ks * 16 + acg));
                vfh[2 * np][0] = m0; vfh[2 * np][1] = m2;
                vfh[2 * np + 1][0] = m1; vfh[2 * np + 1][1] = m3;
                ldsm4(m0, m1, m2, m3, sptr(Vsl + (np * 16 + arow) * ATS + ks * 16 + acg));
                vfl[2 * np][0] = m0; vfl[2 * np][1] = m2;
                vfl[2 * np + 1][0] = m1; vfl[2 * np + 1][1] = m3;
            }
#pragma unroll
            for (int j = 0; j < 8; j++) {
                mma16816(o[j], pal, vfh[j]);
                mma16816(o[j], pah, vfl[j]);
                mma16816(o[j], pah, vfh[j]);
            }
        }
    }

    // ---- epilogue ----
    float inv0 = 1.0f / l0, inv1 = 1.0f / l1;
    int row0 = qb * 64 + warp * 16 + grp;
#pragma unroll
    for (int j = 0; j < 8; j++) {
        int col = h * 64 + 8 * j + 2 * qid;
        float v0 = o[j][0] * inv0, v1 = o[j][1] * inv0;
        __half2 hh = __floats2half2_rn(v0, v1);
        __half2 ll = __floats2half2_rn(v0 - __half2float(__low2half(hh)),
                                       v1 - __half2float(__high2half(hh)));
        size_t i0 = (size_t)(b * SEQ + row0) * DMODEL + col;
        *(__half2*)(Oh + i0) = hh;
        *(__half2*)(Ol + i0) = ll;
        float v2 = o[j][2] * inv1, v3 = o[j][3] * inv1;
        hh = __floats2half2_rn(v2, v3);
        ll = __floats2half2_rn(v2 - __half2float(__low2half(hh)),
                               v3 - __half2float(__high2half(hh)));
        size_t i1 = (size_t)(b * SEQ + row0 + 8) * DMODEL + col;
        *(__half2*)(Oh + i1) = hh;
        *(__half2*)(Ol + i1) = ll;
    }
}

// router attention (full attention within 72 tokens, reconstruct fp32 from planes)
__global__ __launch_bounds__(128) void attn_k(
        const __half* __restrict__ Qh, const __half* __restrict__ Ql,
        const __half* __restrict__ Kh, const __half* __restrict__ Kl,
        const __half* __restrict__ Vh, const __half* __restrict__ Vl,
        __half* __restrict__ Oh, __half* __restrict__ Ol, int SEQ) {
    __shared__ float sq[64];
    __shared__ float sp[128];
    __shared__ float red[128];
    int q = blockIdx.x;
    int bh = blockIdx.y;
    int b = bh / BH, h = bh % BH;
    int tid = threadIdx.x;
    size_t qoff = ((size_t)bh * SEQ + q) * 64;
    if (tid < 64)
        sq[tid] = __half2float(Qh[qoff + tid]) + __half2float(Ql[qoff + tid]);
    __syncthreads();

    float m = -1e30f;
    for (int k = tid; k < SEQ; k += 128) {
        const __half2* krh = (const __half2*)(Kh + ((size_t)bh * SEQ + k) * 64);
        const __half2* krl = (const __half2*)(Kl + ((size_t)bh * SEQ + k) * 64);
        float a = 0.f;
#pragma unroll
        for (int i = 0; i < 32; i++) {
            float2 kh2 = __half22float2(krh[i]);
            float2 kl2 = __half22float2(krl[i]);
            a += (kh2.x + kl2.x) * sq[2 * i] + (kh2.y + kl2.y) * sq[2 * i + 1];
        }
        sp[k] = a * 0.125f;
        m = fmaxf(m, a * 0.125f);
    }
    m = bmax128(m, red);

    float l = 0.f;
    for (int k = tid; k < SEQ; k += 128) {
        float e = __expf(sp[k] - m);
        sp[k] = e;
        l += e;
    }
    l = bsum128(l, red);

    int d = tid & 63, half = tid >> 6;
    float acc = 0.f;
    for (int k = half; k < SEQ; k += 2) {
        size_t vi = ((size_t)bh * SEQ + k) * 64 + d;
        acc += sp[k] * (__half2float(Vh[vi]) + __half2float(Vl[vi]));
    }
    red[tid] = acc;
    __syncthreads();
    if (tid < 64) {
        float o = (red[tid] + red[tid + 64]) / l;
        size_t idx = (size_t)(b * SEQ + q) * DMODEL + h * 64 + tid;
        __half hh, ll;
        split_h(o, hh, ll);
        Oh[idx] = hh;
        Ol[idx] = ll;
    }
}

__global__ void build_xr_k(const float* __restrict__ x, const float* __restrict__ rt,
                           float* __restrict__ xr) {
    int i = blockIdx.x * blockDim.x + threadIdx.x;
    if (i >= NTOK_RTR * DMODEL) return;
    int blk = i / (SRTR * DMODEL);
    int rem = i % (SRTR * DMODEL);
    int t = rem / DMODEL, dd = rem % DMODEL;
    xr[i] = (t < 64) ? x[(size_t)(blk * 64 + t) * DMODEL + dd]
                     : rt[(size_t)(t - 64) * DMODEL + dd];
}

__global__ void gather_rows_k(const float* __restrict__ xr, __half* __restrict__ rh,
                              __half* __restrict__ rl) {
    int i = blockIdx.x * blockDim.x + threadIdx.x;
    if (i >= 512 * DMODEL) return;
    int row = i / DMODEL, dd = i % DMODEL;
    int blk = row >> 3, r = row & 7;
    __half h, l;
    split_h(xr[((size_t)blk * SRTR + 64 + r) * DMODEL + dd], h, l);
    rh[i] = h;
    rl[i] = l;
}

__global__ void knorm_k(const float* __restrict__ kr, const float* __restrict__ kg,
                        float* __restrict__ knr, float* __restrict__ kng) {
    int tid = threadIdx.x;
    int which = tid >> 9;
    int idx = tid & 511;
    int g = idx >> 4, e = idx & 15;
    const float* src = which ? kg : kr;
    const float* col = src + (size_t)g * 128 * 16 + e;
    float s = 0.f;
    for (int d = 0; d < 128; d++) { float v = col[d * 16]; s += v * v; }
    float n = fmaxf(sqrtf(s), 1e-12f);
    if (which) kng[idx] = n; else knr[idx] = n;
}

__global__ void logits_k(const float* __restrict__ outp,
                         const float* __restrict__ keys_r, const float* __restrict__ keys_g,
                         const float* __restrict__ knr, const float* __restrict__ kng,
                         float* __restrict__ rl, float* __restrict__ gl) {
    __shared__ float vr[128], vg[128], red[128];
    int g = blockIdx.x >> 6, bb = blockIdx.x & 63;
    int b = bb >> 5, l = bb & 31;
    int srcl = (l + 31) & 31;
    int r = g >> 2;
    const float* row = outp + (size_t)((b * 32 + srcl) * 8 + r) * 256;
    int tid = threadIdx.x;
    vr[tid] = row[tid];
    vg[tid] = row[128 + tid];
    float nr2 = bsum128(vr[tid] * vr[tid], red);
    float ng2 = bsum128(vg[tid] * vg[tid], red);
    float inr = 1.0f / fmaxf(sqrtf(nr2), 1e-12f);
    float ing = 1.0f / fmaxf(sqrtf(ng2), 1e-12f);
    if (tid < 16) {
        int e = tid;
        const float* kr = keys_r + (size_t)g * 128 * 16 + e;
        const float* kg = keys_g + (size_t)g * 128 * 16 + e;
        float dr = 0.f, dg = 0.f;
        for (int dd = 0; dd < 128; dd++) {
            dr += vr[dd] * kr[dd * 16];
            dg += vg[dd] * kg[dd * 16];
        }
        rl[(size_t)(g * 64 + bb) * 16 + e] = dr * inr / knr[g * 16 + e];
        gl[(size_t)(g * 64 + bb) * 16 + e] = dg * ing / kng[g * 16 + e];
    }
}

__global__ void topk_k(const float* __restrict__ rl, const float* __restrict__ gl,
                       float* __restrict__ out) {
    int t = blockIdx.x * blockDim.x + threadIdx.x;
    if (t >= 2048) return;
    const float* r = rl + (size_t)t * 16;
    const float* g = gl + (size_t)t * 16;
    int i1 = 0; float v1 = r[0];
    for (int e = 1; e < 16; e++) if (r[e] > v1) { v1 = r[e]; i1 = e; }
    int i2 = -1; float v2 = -1e30f;
    for (int e = 0; e < 16; e++) {
        if (e == i1) continue;
        if (r[e] > v2) { v2 = r[e]; i2 = e; }
    }
    out[(size_t)t * 2 + 0] = v1;
    out[(size_t)t * 2 + 1] = v2;
    out[4096 + (size_t)t * 2 + 0] = g[i1];
    out[4096 + (size_t)t * 2 + 1] = g[i2];
}

// ---------------- host orchestration ----------------
static void run_layer(float* cur, size_t qkvo, size_t oo, size_t upo, size_t dno,
                      const float* n1, const float* n2,
                      int ntok, int SEQ, int enc, const int* doc,
                      float* sb, __half* hb_) {
    float*  qkv  = sb + OFF_QKV;
    float*  hbuf = sb + OFF_H;
    __half* xnh = hb_ + HO_XNH; __half* xnl = hb_ + HO_XNL;
    __half* ath = hb_ + HO_ATTH; __half* atl = hb_ + HO_ATTL;
    __half* ach = hb_ + HO_ACTH; __half* acl = hb_ + HO_ACTL;
    __half* wh = hb_ + HO_WH;  __half* wl = hb_ + HO_WL;
    __half* qh_ = hb_ + HO_QH; __half* ql_ = hb_ + HO_QL;
    __half* kh_ = hb_ + HO_KH; __half* kl_ = hb_ + HO_KL;
    __half* vh_ = hb_ + HO_VH; __half* vl_ = hb_ + HO_VL;
    __half* vth_ = hb_ + HO_VTH; __half* vtl_ = hb_ + HO_VTL;
    int bh_total = (ntok / SEQ) * BH;

    rmsnorm_k<<<ntok, 128>>>(cur, n1, xnh, xnl);
    sgemm_h3<<<dim3(1536 / 128, ntok / 128), 256>>>(xnh, xnl, wh + qkvo, wl + qkvo, qkv,
                                                    nullptr, nullptr, ntok, 1536, 512, 0);
    split_rope_k<<<ntok, 256>>>(qkv, qh_, ql_, kh_, kl_, vh_, vl_, SEQ);
    if (enc) {
        vtrans_k<<<dim3(SEQ / 64, bh_total), 256>>>(vh_, vl_, vth_, vtl_, SEQ);
        attn_mma_k<<<dim3(SEQ / 64, bh_total), 128, AMMA_SMEM>>>(
            qh_, ql_, kh_, kl_, vth_, vtl_, ath, atl, doc, SEQ);
    } else {
        attn_k<<<dim3(SEQ, bh_total), 128>>>(qh_, ql_, kh_, kl_, vh_, vl_, ath, atl, SEQ);
    }
    sgemm_h3<<<dim3(512 / 128, ntok / 128), 256>>>(ath, atl, wh + oo, wl + oo, cur,
                                                   nullptr, nullptr, ntok, 512, 512, 1);
    rmsnorm_k<<<ntok, 128>>>(cur, n2, xnh, xnl);
    sgemm_h3<<<dim3(2048 / 128, ntok / 128), 256>>>(xnh, xnl, wh + upo, wl + upo, hbuf,
                                                    ach, acl, ntok, 2048, 512, 2);
    sgemm_h3<<<dim3(512 / 128, ntok / 128), 256>>>(ach, acl, wh + dno, wl + dno, cur,
                                                   nullptr, nullptr, ntok, 512, 1024, 1);
}

extern "C" void kernel_launch(void* const* d_in, const int* in_sizes, int n_in,
                              void* d_out, int out_size) {
    const float* x_in   = (const float*)d_in[0];
    const int*   doc    = (const int*)d_in[1];
    const float* rt     = (const float*)d_in[2];
    const float* out_w  = (const float*)d_in[3];
    const float* keys_r = (const float*)d_in[4];
    const float* keys_g = (const float*)d_in[5];
    const float* e_qkv  = (const float*)d_in[6];
    const float* e_o    = (const float*)d_in[7];
    const float* e_up   = (const float*)d_in[8];
    const float* e_dn   = (const float*)d_in[9];
    const float* e_n1   = (const float*)d_in[10];
    const float* e_n2   = (const float*)d_in[11];
    const float* r_qkv  = (const float*)d_in[12];
    const float* r_o    = (const float*)d_in[13];
    const float* r_up   = (const float*)d_in[14];
    const float* r_dn   = (const float*)d_in[15];
    const float* r_n1   = (const float*)d_in[16];
    const float* r_n2   = (const float*)d_in[17];
    float* out = (float*)d_out;

    static int smem_set = 0;
    if (!smem_set) {
        cudaFuncSetAttribute(attn_mma_k, cudaFuncAttributeMaxDynamicSharedMemorySize, AMMA_SMEM);
        smem_set = 1;
    }

    float* sb;
    cudaGetSymbolAddress((void**)&sb, g_s);
    __half* hb_;
    cudaGetSymbolAddress((void**)&hb_, g_h);

    float* xbuf = sb + OFF_X;
    float* xr   = sb + OFF_XR;
    float* outp = sb + OFF_OUT;
    float* knr  = sb + OFF_KNR;
    float* kng  = sb + OFF_KNG;
    float* rl   = sb + OFF_RL;
    float* gl   = sb + OFF_GL;
    __half* wh = hb_ + HO_WH;
    __half* wl = hb_ + HO_WL;
    __half* rowsh = hb_ + HO_ROWSH;
    __half* rowsl = hb_ + HO_ROWSL;

    for (int i = 0; i < 4; i++) {
        wsplitT_k<<<dim3(1536 / 32, 512 / 32), dim3(32, 8)>>>(
            e_qkv + (size_t)i * 512 * 1536, wh + WO_EQ + (size_t)i * 786432,
            wl + WO_EQ + (size_t)i * 786432, 512, 1536, 0);
        wsplitT_k<<<dim3(512 / 32, 512 / 32), dim3(32, 8)>>>(
            e_o + (size_t)i * 512 * 512, wh + WO_EO + (size_t)i * 262144,
            wl + WO_EO + (size_t)i * 262144, 512, 512, 0);
        wsplitT_k<<<dim3(2048 / 32, 512 / 32), dim3(32, 8)>>>(
            e_up + (size_t)i * 512 * 2048, wh + WO_EU + (size_t)i * 1048576,
            wl + WO_EU + (size_t)i * 1048576, 512, 2048, 1);
        wsplitT_k<<<dim3(512 / 32, 1024 / 32), dim3(32, 8)>>>(
            e_dn + (size_t)i * 1024 * 512, wh + WO_ED + (size_t)i * 524288,
            wl + WO_ED + (size_t)i * 524288, 1024, 512, 0);
    }
    for (int i = 0; i < 2; i++) {
        wsplitT_k<<<dim3(1536 / 32, 512 / 32), dim3(32, 8)>>>(
            r_qkv + (size_t)i * 512 * 1536, wh + WO_RQ + (size_t)i * 786432,
            wl + WO_RQ + (size_t)i * 786432, 512, 1536, 0);
        wsplitT_k<<<dim3(512 / 32, 512 / 32), dim3(32, 8)>>>(
            r_o + (size_t)i * 512 * 512, wh + WO_RO + (size_t)i * 262144,
            wl + WO_RO + (size_t)i * 262144, 512, 512, 0);
        wsplitT_k<<<dim3(2048 / 32, 512 / 32), dim3(32, 8)>>>(
            r_up + (size_t)i * 512 * 2048, wh + WO_RU + (size_t)i * 1048576,
            wl + WO_RU + (size_t)i * 1048576, 512, 2048, 1);
        wsplitT_k<<<dim3(512 / 32, 1024 / 32), dim3(32, 8)>>>(
            r_dn + (size_t)i * 1024 * 512, wh + WO_RD + (size_t)i * 524288,
            wl + WO_RD + (size_t)i * 524288, 1024, 512, 0);
    }
    wsplitT_k<<<dim3(256 / 32, 512 / 32), dim3(32, 8)>>>(out_w, wh + WO_OUT, wl + WO_OUT, 512, 256, 0);

    copy_k<<<(NTOK_ENC * DMODEL + 255) / 256, 256>>>(x_in, xbuf, NTOK_ENC * DMODEL);

    for (int i = 0; i < 4; i++) {
        run_layer(xbuf,
                  WO_EQ + (size_t)i * 786432,
                  WO_EO + (size_t)i * 262144,
                  WO_EU + (size_t)i * 1048576,
                  WO_ED + (size_t)i * 524288,
                  e_n1 + (size_t)i * 512, e_n2 + (size_t)i * 512,
                  NTOK_ENC, SENC, 1, doc, sb, hb_);
    }

    build_xr_k<<<(NTOK_RTR * DMODEL + 255) / 256, 256>>>(xbuf, rt, xr);

    for (int i = 0; i < 2; i++) {
        run_layer(xr,
                  WO_RQ + (size_t)i * 786432,
                  WO_RO + (size_t)i * 262144,
                  WO_RU + (size_t)i * 1048576,
                  WO_RD + (size_t)i * 524288,
                  r_n1 + (size_t)i * 512, r_n2 + (size_t)i * 512,
                  NTOK_RTR, SRTR, 0, nullptr, sb, hb_);
    }

    gather_rows_k<<<(512 * DMODEL + 255) / 256, 256>>>(xr, rowsh, rowsl);
    sgemm_h3<<<dim3(256 / 128, 512 / 128), 256>>>(rowsh, rowsl, wh + WO_OUT, wl + WO_OUT, outp,
                                                  nullptr, nullptr, 512, 256, 512, 0);

    knorm_k<<<1, 1024>>>(keys_r, keys_g, knr, kng);
    logits_k<<<32 * 64, 128>>>(outp, keys_r, keys_g, knr, kng, rl, gl);
    topk_k<<<16, 128>>>(rl, gl, out);
}